// round 5
// baseline (speedup 1.0000x reference)
#include <cuda_runtime.h>
#include <cuda_bf16.h>
#include <math.h>
#include <stdint.h>

#define HIDK 1024
#define MTOK 4096
#define LSEQ 2048
#define NHEAD 16
#define HDIM 64
#define CT 64
#define NCH (LSEQ / CT)
#define PD 68

// ---------------- scratch (device globals; no allocations) ----------------
__device__ float g_q[MTOK * HIDK];
__device__ float g_k[MTOK * HIDK];
__device__ float g_v[MTOK * HIDK];
__device__ float g_xg[MTOK * HIDK];
__device__ float g_gk[MTOK * HIDK];
__device__ float g_att[MTOK * HIDK];
__device__ float g_t[MTOK * 16];
__device__ float g_expD[MTOK * HIDK];
__device__ float g_P[32 * NCH * HDIM * HDIM];
__device__ float g_S[32 * NCH * HDIM * HDIM];
// bf16 split operands
__device__ __align__(16) __nv_bfloat16 g_xh[MTOK * HIDK];
__device__ __align__(16) __nv_bfloat16 g_xl[MTOK * HIDK];
__device__ __align__(16) __nv_bfloat16 g_yh[MTOK * HIDK];
__device__ __align__(16) __nv_bfloat16 g_yl[MTOK * HIDK];
__device__ __align__(16) __nv_bfloat16 g_wh[5 * HIDK * HIDK];  // transposed [n][k]
__device__ __align__(16) __nv_bfloat16 g_wl[5 * HIDK * HIDK];

// ======================= helpers =======================
__device__ __forceinline__ uint32_t smem_u32(const void* p) {
    uint32_t a;
    asm("{ .reg .u64 t; cvta.to.shared.u64 t, %1; cvt.u32.u64 %0, t; }" : "=r"(a) : "l"(p));
    return a;
}
__device__ __forceinline__ void cpasync16(uint32_t s, const void* g) {
    asm volatile("cp.async.cg.shared.global [%0], [%1], 16;" ::"r"(s), "l"(g));
}
__device__ __forceinline__ void cpcommit() { asm volatile("cp.async.commit_group;"); }

__device__ __forceinline__ void ldmx4(uint32_t& r0, uint32_t& r1, uint32_t& r2,
                                      uint32_t& r3, uint32_t addr) {
    asm volatile("ldmatrix.sync.aligned.m8n8.x4.shared.b16 {%0,%1,%2,%3}, [%4];"
                 : "=r"(r0), "=r"(r1), "=r"(r2), "=r"(r3)
                 : "r"(addr));
}
__device__ __forceinline__ void mma16816(float* c, const uint32_t* a, const uint32_t* b) {
    asm volatile(
        "mma.sync.aligned.m16n8k16.row.col.f32.bf16.bf16.f32 "
        "{%0,%1,%2,%3}, {%4,%5,%6,%7}, {%8,%9}, {%0,%1,%2,%3};"
        : "+f"(c[0]), "+f"(c[1]), "+f"(c[2]), "+f"(c[3])
        : "r"(a[0]), "r"(a[1]), "r"(a[2]), "r"(a[3]), "r"(b[0]), "r"(b[1]));
}

// ======================= bf16 mma.sync GEMM =======================
// C[M,1024] = A(hi+lo) @ W(hi+lo)^T via 3 split products computed from ONE
// smem residency per K-chunk (Ah|Al|Bh|Bl loaded together).
#define ROWB 80                  // 32 bf16 (64B) + 16B pad per row
#define BLKB (128 * ROWB)        // 10240 bytes per operand block
#define STG (4 * BLKB)           // 40960 bytes per stage
#define NSTG 3
#define SMEM_MM (NSTG * STG)     // 122880 bytes
#define NCHK 32                  // 1024 / 32

__device__ __forceinline__ void mm_issue(int s, uint32_t sb, int tid, int brow, int bcol,
                                         const __nv_bfloat16* Ah, const __nv_bfloat16* Al,
                                         const __nv_bfloat16* Bh, const __nv_bfloat16* Bl) {
    if (s < NCHK) {
        int kk = s << 5;
        uint32_t st = sb + (uint32_t)(s % NSTG) * STG;
        int row = tid >> 2, cw = tid & 3;
        uint32_t so = row * ROWB + cw * 16;
        size_t goA = (size_t)(brow + row) * HIDK + kk + cw * 8;
        cpasync16(st + so, Ah + goA);
        cpasync16(st + 64 * ROWB + so, Ah + goA + (size_t)64 * HIDK);
        cpasync16(st + BLKB + so, Al + goA);
        cpasync16(st + BLKB + 64 * ROWB + so, Al + goA + (size_t)64 * HIDK);
        size_t goB = (size_t)(bcol + row) * HIDK + kk + cw * 8;
        cpasync16(st + 2 * BLKB + so, Bh + goB);
        cpasync16(st + 2 * BLKB + 64 * ROWB + so, Bh + goB + (size_t)64 * HIDK);
        cpasync16(st + 3 * BLKB + so, Bl + goB);
        cpasync16(st + 3 * BLKB + 64 * ROWB + so, Bl + goB + (size_t)64 * HIDK);
    }
    cpcommit();
}

__device__ __forceinline__ void mma_gemm_body(const __nv_bfloat16* __restrict__ Ah,
                                              const __nv_bfloat16* __restrict__ Al,
                                              const __nv_bfloat16* __restrict__ Bh,
                                              const __nv_bfloat16* __restrict__ Bl,
                                              float* __restrict__ C) {
    extern __shared__ char sm_raw[];
    uint32_t sb = smem_u32(sm_raw);
    int tid = threadIdx.x, lane = tid & 31, wid = tid >> 5;
    int wm = wid & 3, wn = wid >> 2;
    int brow = blockIdx.y * 128, bcol = blockIdx.x * 128;

    float c[2][8][4];
#pragma unroll
    for (int i = 0; i < 2; i++)
#pragma unroll
        for (int j = 0; j < 8; j++)
#pragma unroll
            for (int l = 0; l < 4; l++) c[i][j][l] = 0.f;

    mm_issue(0, sb, tid, brow, bcol, Ah, Al, Bh, Bl);
    mm_issue(1, sb, tid, brow, bcol, Ah, Al, Bh, Bl);
    mm_issue(2, sb, tid, brow, bcol, Ah, Al, Bh, Bl);

    int q = lane >> 3, r = lane & 7;

    for (int s = 0; s < NCHK; s++) {
        asm volatile("cp.async.wait_group 2;" ::: "memory");
        __syncthreads();
        uint32_t st = sb + (uint32_t)(s % NSTG) * STG;
#pragma unroll
        for (int k0 = 0; k0 < 32; k0 += 16) {
            uint32_t ah[2][4], al[2][4], bh[8][2], bl[8][2];
            int arow = wm * 32 + (q & 1) * 8 + r;
            int akc = (k0 + (q >> 1) * 8) * 2;
#pragma unroll
            for (int mf = 0; mf < 2; mf++)
                ldmx4(ah[mf][0], ah[mf][1], ah[mf][2], ah[mf][3],
                      st + (arow + mf * 16) * ROWB + akc);
            int nrow = wn * 64 + (q >> 1) * 8 + r;
            int bkc = (k0 + (q & 1) * 8) * 2;
#pragma unroll
            for (int pb = 0; pb < 4; pb++) {
                uint32_t r0, r1, r2, r3;
                ldmx4(r0, r1, r2, r3, st + 2 * BLKB + (nrow + pb * 16) * ROWB + bkc);
                bh[pb * 2][0] = r0; bh[pb * 2][1] = r1;
                bh[pb * 2 + 1][0] = r2; bh[pb * 2 + 1][1] = r3;
            }
            // product 1: Ah x Bh
#pragma unroll
            for (int mf = 0; mf < 2; mf++)
#pragma unroll
                for (int nf = 0; nf < 8; nf++) mma16816(c[mf][nf], ah[mf], bh[nf]);
            // product 2: Al x Bh
#pragma unroll
            for (int mf = 0; mf < 2; mf++)
                ldmx4(al[mf][0], al[mf][1], al[mf][2], al[mf][3],
                      st + BLKB + (arow + mf * 16) * ROWB + akc);
#pragma unroll
            for (int mf = 0; mf < 2; mf++)
#pragma unroll
                for (int nf = 0; nf < 8; nf++) mma16816(c[mf][nf], al[mf], bh[nf]);
            // product 3: Ah x Bl
#pragma unroll
            for (int pb = 0; pb < 4; pb++) {
                uint32_t r0, r1, r2, r3;
                ldmx4(r0, r1, r2, r3, st + 3 * BLKB + (nrow + pb * 16) * ROWB + bkc);
                bl[pb * 2][0] = r0; bl[pb * 2][1] = r1;
                bl[pb * 2 + 1][0] = r2; bl[pb * 2 + 1][1] = r3;
            }
#pragma unroll
            for (int mf = 0; mf < 2; mf++)
#pragma unroll
                for (int nf = 0; nf < 8; nf++) mma16816(c[mf][nf], ah[mf], bl[nf]);
        }
        __syncthreads();
        mm_issue(s + 3, sb, tid, brow, bcol, Ah, Al, Bh, Bl);
    }

    int qr = lane >> 2, qc = lane & 3;
#pragma unroll
    for (int mf = 0; mf < 2; mf++)
#pragma unroll
        for (int nf = 0; nf < 8; nf++) {
            int row0 = brow + wm * 32 + mf * 16 + qr;
            int col = bcol + wn * 64 + nf * 8 + qc * 2;
            *(float2*)&C[(size_t)row0 * HIDK + col] = make_float2(c[mf][nf][0], c[mf][nf][1]);
            *(float2*)&C[(size_t)(row0 + 8) * HIDK + col] = make_float2(c[mf][nf][2], c[mf][nf][3]);
        }
}

__global__ void __launch_bounds__(256) mmproj_kernel() {
    int z = blockIdx.z;
    const __nv_bfloat16* Bh = g_wh + (size_t)z * HIDK * HIDK;
    const __nv_bfloat16* Bl = g_wl + (size_t)z * HIDK * HIDK;
    float* C = (z == 0) ? g_q : (z == 1) ? g_k : (z == 2) ? g_v : g_xg;
    mma_gemm_body(g_xh, g_xl, Bh, Bl, C);
}
__global__ void __launch_bounds__(256) mmout_kernel(float* __restrict__ out) {
    mma_gemm_body(g_yh, g_yl, g_wh + (size_t)4 * HIDK * HIDK,
                  g_wl + (size_t)4 * HIDK * HIDK, out);
}

// ======================= conversion kernels =======================
__global__ void __launch_bounds__(256) xconv_kernel(const float* __restrict__ x) {
    size_t i = (size_t)blockIdx.x * 256 + threadIdx.x;
    float4 v = ((const float4*)x)[i];
    __nv_bfloat16 h0 = __float2bfloat16(v.x), h1 = __float2bfloat16(v.y);
    __nv_bfloat16 h2 = __float2bfloat16(v.z), h3 = __float2bfloat16(v.w);
    __nv_bfloat162* ph = (__nv_bfloat162*)g_xh;
    __nv_bfloat162* pl = (__nv_bfloat162*)g_xl;
    ph[2 * i] = __nv_bfloat162(h0, h1);
    ph[2 * i + 1] = __nv_bfloat162(h2, h3);
    pl[2 * i] = __nv_bfloat162(__float2bfloat16(v.x - __bfloat162float(h0)),
                               __float2bfloat16(v.y - __bfloat162float(h1)));
    pl[2 * i + 1] = __nv_bfloat162(__float2bfloat16(v.z - __bfloat162float(h2)),
                                   __float2bfloat16(v.w - __bfloat162float(h3)));
}

// transpose + split: Wt[n][k] = W[k][n]
__global__ void __launch_bounds__(256) wconv_kernel(const float* __restrict__ W0,
                                                    const float* __restrict__ W1,
                                                    const float* __restrict__ W2,
                                                    const float* __restrict__ W3,
                                                    const float* __restrict__ W4) {
    int z = blockIdx.z;
    const float* W = (z == 0) ? W0 : (z == 1) ? W1 : (z == 2) ? W2 : (z == 3) ? W3 : W4;
    __nv_bfloat16* Th = g_wh + (size_t)z * HIDK * HIDK;
    __nv_bfloat16* Tl = g_wl + (size_t)z * HIDK * HIDK;
    __shared__ float t[32][33];
    int n0 = blockIdx.x * 32, k0 = blockIdx.y * 32;
    int lx = threadIdx.x & 31, ly = threadIdx.x >> 5;
#pragma unroll
    for (int i = 0; i < 4; i++) {
        int r = ly + i * 8;
        t[r][lx] = W[(size_t)(k0 + r) * HIDK + n0 + lx];
    }
    __syncthreads();
#pragma unroll
    for (int i = 0; i < 4; i++) {
        int r = ly + i * 8;
        float v = t[lx][r];  // = W[k0+lx][n0+r]
        __nv_bfloat16 h = __float2bfloat16(v);
        size_t o = (size_t)(n0 + r) * HIDK + k0 + lx;
        Th[o] = h;
        Tl[o] = __float2bfloat16(v - __bfloat162float(h));
    }
}

// ---------------- low-rank gate path ---------------------------------------
__global__ void __launch_bounds__(256) lr1_kernel(const float* __restrict__ x,
                                                  const float* __restrict__ W1) {
    int tid = threadIdx.x;
    int r = tid & 15;
    int ml = tid >> 4;
    int m = blockIdx.x * 16 + ml;
    const float* xr = x + (size_t)m * HIDK;
    float acc = 0.f;
#pragma unroll 4
    for (int kk = 0; kk < HIDK; kk++) acc = fmaf(xr[kk], W1[kk * 16 + r], acc);
    g_t[m * 16 + r] = acc;
}

// W2 staged in smem once per block; 16 m-rows per block.
__global__ void __launch_bounds__(256) lr2_kernel(const float* __restrict__ W2,
                                                  const float* __restrict__ bias) {
    extern __shared__ float w2s[];  // [16][1024]
    int tid = threadIdx.x;
#pragma unroll
    for (int i = 0; i < 16; i++) {
        int idx = tid + i * 256;  // 4096 float4 total
        ((float4*)w2s)[idx] = ((const float4*)W2)[idx];
    }
    __syncthreads();
    int n = tid * 4;
    float4 b4 = *(const float4*)(bias + n);
    int m0 = blockIdx.x * 16;
#pragma unroll 1
    for (int mi = 0; mi < 16; mi++) {
        int m = m0 + mi;
        float4 a = b4;
#pragma unroll
        for (int r = 0; r < 16; r++) {
            float tv = g_t[m * 16 + r];
            float4 w = *(float4*)&w2s[r * 1024 + n];
            a.x = fmaf(tv, w.x, a.x);
            a.y = fmaf(tv, w.y, a.y);
            a.z = fmaf(tv, w.z, a.z);
            a.w = fmaf(tv, w.w, a.w);
        }
        float4 o;
        o.x = (fminf(a.x, 0.f) - log1pf(__expf(-fabsf(a.x)))) * 0.0625f;
        o.y = (fminf(a.y, 0.f) - log1pf(__expf(-fabsf(a.y)))) * 0.0625f;
        o.z = (fminf(a.z, 0.f) - log1pf(__expf(-fabsf(a.z)))) * 0.0625f;
        o.w = (fminf(a.w, 0.f) - log1pf(__expf(-fabsf(a.w)))) * 0.0625f;
        *(float4*)(g_gk + (size_t)m * HIDK + n) = o;
    }
}

// ---------------- chunked GLA: kernel A (intra-chunk + summaries) ----------
__global__ void __launch_bounds__(256) chunk_kernel() {
    extern __shared__ float sm[];
    float* sQt = sm;
    float* sKt = sm + 64 * PD;
    float* sK = sm + 2 * 64 * PD;
    float* sU = sm + 3 * 64 * PD;
    float* sAV = sm + 4 * 64 * PD;
    float* sED = sm + 5 * 64 * PD;

    int c = blockIdx.x, bh = blockIdx.y;
    int b = bh >> 4, h = bh & 15;
    int tid = threadIdx.x;
    size_t rowbase = (size_t)(b * LSEQ + c * CT) * HIDK + h * HDIM;

#pragma unroll
    for (int i = 0; i < 4; i++) {
        int idx = tid + i * 256;
        int t = idx >> 4, c4 = (idx & 15) << 2;
        size_t gi = rowbase + (size_t)t * HIDK + c4;
        float4 q4 = *(const float4*)(g_q + gi);
        float4 k4 = *(const float4*)(g_k + gi);
        float4 v4 = *(const float4*)(g_v + gi);
        float4 gg = *(const float4*)(g_gk + gi);
        sQt[(c4 + 0) * PD + t] = q4.x;
        sQt[(c4 + 1) * PD + t] = q4.y;
        sQt[(c4 + 2) * PD + t] = q4.z;
        sQt[(c4 + 3) * PD + t] = q4.w;
        sKt[(c4 + 0) * PD + t] = k4.x;
        sKt[(c4 + 1) * PD + t] = k4.y;
        sKt[(c4 + 2) * PD + t] = k4.z;
        sKt[(c4 + 3) * PD + t] = k4.w;
        *(float4*)&sK[t * PD + c4] = k4;
        *(float4*)&sAV[t * PD + c4] = v4;
        *(float4*)&sED[t * PD + c4] = gg;
    }
    __syncthreads();

    if (tid < 64) {
        float run = 0.f;
        for (int t = 0; t < CT; t++) {
            run += sED[t * PD + tid];
            sED[t * PD + tid] = __expf(run);
            sU[t * PD + tid] = __expf(-run) * sAV[t * PD + tid];
        }
    }
    __syncthreads();

#pragma unroll
    for (int i = 0; i < 4; i++) {
        int idx = tid + i * 256;
        int t = idx >> 4, c4 = (idx & 15) << 2;
        *(float4*)(g_expD + rowbase + (size_t)t * HIDK + c4) = *(float4*)&sED[t * PD + c4];
    }

    {
        int t0 = (tid & 15) << 2, s0 = (tid >> 4) << 2;
        float acc[4][4];
#pragma unroll
        for (int i = 0; i < 4; i++)
#pragma unroll
            for (int j = 0; j < 4; j++) acc[i][j] = 0.f;
        for (int d = 0; d < 64; d++) {
            float4 a = *(float4*)&sQt[d * PD + t0];
            float4 bb = *(float4*)&sKt[d * PD + s0];
            float av[4] = {a.x, a.y, a.z, a.w};
            float bv[4] = {bb.x, bb.y, bb.z, bb.w};
#pragma unroll
            for (int i = 0; i < 4; i++)
#pragma unroll
                for (int j = 0; j < 4; j++) acc[i][j] = fmaf(av[i], bv[j], acc[i][j]);
        }
#pragma unroll
        for (int j = 0; j < 4; j++) {
            int s = s0 + j;
            float4 o;
            o.x = (s <= t0 + 0) ? acc[0][j] : 0.f;
            o.y = (s <= t0 + 1) ? acc[1][j] : 0.f;
            o.z = (s <= t0 + 2) ? acc[2][j] : 0.f;
            o.w = (s <= t0 + 3) ? acc[3][j] : 0.f;
            *(float4*)&sAV[s * PD + t0] = o;
        }
    }
    __syncthreads();

    int r0 = (tid >> 4) << 2, c0 = (tid & 15) << 2;

    {
        float acc[4][4];
#pragma unroll
        for (int i = 0; i < 4; i++)
#pragma unroll
            for (int j = 0; j < 4; j++) acc[i][j] = 0.f;
        for (int s = 0; s < CT; s++) {
            float4 a = *(float4*)&sAV[s * PD + r0];
            float4 bb = *(float4*)&sU[s * PD + c0];
            float av[4] = {a.x, a.y, a.z, a.w};
            float bv[4] = {bb.x, bb.y, bb.z, bb.w};
#pragma unroll
            for (int i = 0; i < 4; i++)
#pragma unroll
                for (int j = 0; j < 4; j++) acc[i][j] = fmaf(av[i], bv[j], acc[i][j]);
        }
#pragma unroll
        for (int i = 0; i < 4; i++) {
            int t = r0 + i;
            float4 e = *(float4*)&sED[t * PD + c0];
            float4 o = make_float4(acc[i][0] * e.x, acc[i][1] * e.y, acc[i][2] * e.z,
                                   acc[i][3] * e.w);
            *(float4*)(g_att + rowbase + (size_t)t * HIDK + c0) = o;
        }
    }

    {
        float acc[4][4];
#pragma unroll
        for (int i = 0; i < 4; i++)
#pragma unroll
            for (int j = 0; j < 4; j++) acc[i][j] = 0.f;
        for (int s = 0; s < CT; s++) {
            float4 a = *(float4*)&sU[s * PD + r0];
            float4 bb = *(float4*)&sK[s * PD + c0];
            float av[4] = {a.x, a.y, a.z, a.w};
            float bv[4] = {bb.x, bb.y, bb.z, bb.w};
#pragma unroll
            for (int i = 0; i < 4; i++)
#pragma unroll
                for (int j = 0; j < 4; j++) acc[i][j] = fmaf(av[i], bv[j], acc[i][j]);
        }
        size_t pbase = ((size_t)(bh * NCH + c)) << 12;
#pragma unroll
        for (int i = 0; i < 4; i++) {
            float ev = sED[63 * PD + r0 + i];
            float4 o = make_float4(acc[i][0] * ev, acc[i][1] * ev, acc[i][2] * ev,
                                   acc[i][3] * ev);
            *(float4*)(g_P + pbase + ((size_t)(r0 + i) << 6) + c0) = o;
        }
    }
}

// ---------------- kernel B: scan over chunk states --------------------------
__global__ void __launch_bounds__(512) chunkscan_kernel() {
    int bh = blockIdx.x;
    int b = bh >> 4, h = bh & 15;
    int tid = threadIdx.x;
    int v = tid >> 3;
    int k0 = (tid & 7) << 3;
    float S[8];
#pragma unroll
    for (int j = 0; j < 8; j++) S[j] = 0.f;

    for (int c = 0; c < NCH; c++) {
        size_t base = (((size_t)(bh * NCH + c)) << 12) + ((size_t)v << 6) + k0;
        *(float4*)(g_S + base) = make_float4(S[0], S[1], S[2], S[3]);
        *(float4*)(g_S + base + 4) = make_float4(S[4], S[5], S[6], S[7]);
        float E = g_expD[((size_t)(b * LSEQ + c * CT + 63)) * HIDK + h * HDIM + v];
        float4 p0 = *(float4*)(g_P + base);
        float4 p1 = *(float4*)(g_P + base + 4);
        S[0] = fmaf(S[0], E, p0.x);
        S[1] = fmaf(S[1], E, p0.y);
        S[2] = fmaf(S[2], E, p0.z);
        S[3] = fmaf(S[3], E, p0.w);
        S[4] = fmaf(S[4], E, p1.x);
        S[5] = fmaf(S[5], E, p1.y);
        S[6] = fmaf(S[6], E, p1.z);
        S[7] = fmaf(S[7], E, p1.w);
    }
}

// ---------------- kernel C: inter-chunk output ------------------------------
__global__ void __launch_bounds__(256) inter_kernel() {
    __shared__ float sQt[64 * PD];
    __shared__ float sSt[64 * PD];
    int c = blockIdx.x, bh = blockIdx.y;
    int b = bh >> 4, h = bh & 15;
    int tid = threadIdx.x;
    size_t rowbase = (size_t)(b * LSEQ + c * CT) * HIDK + h * HDIM;
    size_t sbase = ((size_t)(bh * NCH + c)) << 12;

#pragma unroll
    for (int i = 0; i < 4; i++) {
        int idx = tid + i * 256;
        int t = idx >> 4, c4 = (idx & 15) << 2;
        float4 q4 = *(const float4*)(g_q + rowbase + (size_t)t * HIDK + c4);
        sQt[(c4 + 0) * PD + t] = q4.x;
        sQt[(c4 + 1) * PD + t] = q4.y;
        sQt[(c4 + 2) * PD + t] = q4.z;
        sQt[(c4 + 3) * PD + t] = q4.w;
        float4 s4 = *(const float4*)(g_S + sbase + ((size_t)t << 6) + c4);
        sSt[(c4 + 0) * PD + t] = s4.x;
        sSt[(c4 + 1) * PD + t] = s4.y;
        sSt[(c4 + 2) * PD + t] = s4.z;
        sSt[(c4 + 3) * PD + t] = s4.w;
    }
    __syncthreads();

    int t0 = (tid >> 4) << 2, v0 = (tid & 15) << 2;
    float acc[4][4];
#pragma unroll
    for (int i = 0; i < 4; i++)
#pragma unroll
        for (int j = 0; j < 4; j++) acc[i][j] = 0.f;
    for (int k = 0; k < 64; k++) {
        float4 a = *(float4*)&sQt[k * PD + t0];
        float4 bb = *(float4*)&sSt[k * PD + v0];
        float av[4] = {a.x, a.y, a.z, a.w};
        float bv[4] = {bb.x, bb.y, bb.z, bb.w};
#pragma unroll
        for (int i = 0; i < 4; i++)
#pragma unroll
            for (int j = 0; j < 4; j++) acc[i][j] = fmaf(av[i], bv[j], acc[i][j]);
    }
#pragma unroll
    for (int i = 0; i < 4; i++) {
        int t = t0 + i;
        size_t gi = rowbase + (size_t)t * HIDK + v0;
        float4 e = *(float4*)(g_expD + gi);
        float4 o = *(float4*)(g_att + gi);
        o.x = fmaf(acc[i][0], e.x, o.x);
        o.y = fmaf(acc[i][1], e.y, o.y);
        o.z = fmaf(acc[i][2], e.z, o.z);
        o.w = fmaf(acc[i][3], e.w, o.w);
        *(float4*)(g_att + gi) = o;
    }
}

// ---------------- LayerNorm + SiLU gate -> bf16-split y ---------------------
__global__ void __launch_bounds__(256) ln_gate_kernel(const float* __restrict__ gamma,
                                                      const float* __restrict__ beta) {
    int row = blockIdx.x;
    int tid = threadIdx.x;
    const float* a = g_att + (size_t)row * HIDK;
    float vals[4];
    float s = 0.f, s2 = 0.f;
#pragma unroll
    for (int i = 0; i < 4; i++) {
        vals[i] = a[i * 256 + tid];
        s += vals[i];
        s2 = fmaf(vals[i], vals[i], s2);
    }
#pragma unroll
    for (int o = 16; o; o >>= 1) {
        s += __shfl_xor_sync(0xffffffffu, s, o);
        s2 += __shfl_xor_sync(0xffffffffu, s2, o);
    }
    __shared__ float rs[8], rs2[8];
    int warp = tid >> 5;
    if ((tid & 31) == 0) { rs[warp] = s; rs2[warp] = s2; }
    __syncthreads();
    s = 0.f;
    s2 = 0.f;
#pragma unroll
    for (int w = 0; w < 8; w++) { s += rs[w]; s2 += rs2[w]; }
    float mean = s * (1.f / HIDK);
    float var = s2 * (1.f / HIDK) - mean * mean;
    float rstd = rsqrtf(var + 1e-5f);
#pragma unroll
    for (int i = 0; i < 4; i++) {
        int col = i * 256 + tid;
        float gv = g_xg[(size_t)row * HIDK + col];
        float sil = gv / (1.f + __expf(-gv));
        float yv = ((vals[i] - mean) * rstd * gamma[col] + beta[col]) * sil;
        __nv_bfloat16 h = __float2bfloat16(yv);
        g_yh[(size_t)row * HIDK + col] = h;
        g_yl[(size_t)row * HIDK + col] = __float2bfloat16(yv - __bfloat162float(h));
    }
}

// ---------------- launch --------------------------------------------------
extern "C" void kernel_launch(void* const* d_in, const int* in_sizes, int n_in,
                              void* d_out, int out_size) {
    const float* x = (const float*)d_in[0];
    const float* Wq = (const float*)d_in[1];
    const float* Wk = (const float*)d_in[2];
    const float* Wv = (const float*)d_in[3];
    const float* Wg = (const float*)d_in[4];
    const float* Wgk1 = (const float*)d_in[5];
    const float* Wgk2 = (const float*)d_in[6];
    const float* bgk2 = (const float*)d_in[7];
    const float* gamma = (const float*)d_in[8];
    const float* beta = (const float*)d_in[9];
    const float* Wout = (const float*)d_in[10];
    float* out = (float*)d_out;

    const int SMEM_A = 6 * 64 * PD * sizeof(float);
    const int SMEM_LR2 = 16 * 1024 * sizeof(float);
    cudaFuncSetAttribute(chunk_kernel, cudaFuncAttributeMaxDynamicSharedMemorySize, SMEM_A);
    cudaFuncSetAttribute(mmproj_kernel, cudaFuncAttributeMaxDynamicSharedMemorySize, SMEM_MM);
    cudaFuncSetAttribute(mmout_kernel, cudaFuncAttributeMaxDynamicSharedMemorySize, SMEM_MM);
    cudaFuncSetAttribute(lr2_kernel, cudaFuncAttributeMaxDynamicSharedMemorySize, SMEM_LR2);

    xconv_kernel<<<MTOK * HIDK / 1024, 256>>>(x);
    wconv_kernel<<<dim3(32, 32, 5), 256>>>(Wq, Wk, Wv, Wg, Wout);
    lr1_kernel<<<MTOK / 16, 256>>>(x, Wgk1);
    lr2_kernel<<<MTOK / 16, 256, SMEM_LR2>>>(Wgk2, bgk2);

    mmproj_kernel<<<dim3(8, 32, 4), 256, SMEM_MM>>>();

    chunk_kernel<<<dim3(NCH, 32), 256, SMEM_A>>>();
    chunkscan_kernel<<<32, 512>>>();
    inter_kernel<<<dim3(NCH, 32), 256>>>();
    ln_gate_kernel<<<MTOK, 256>>>(gamma, beta);

    mmout_kernel<<<dim3(8, 32, 1), 256, SMEM_MM>>>(out);
}

// round 6
// speedup vs baseline: 1.1468x; 1.1468x over previous
#include <cuda_runtime.h>
#include <cuda_bf16.h>
#include <math.h>
#include <stdint.h>

#define HIDK 1024
#define MTOK 4096
#define LSEQ 2048
#define NHEAD 16
#define HDIM 64
#define CT 64
#define NCH (LSEQ / CT)
#define PD 68

// ---------------- scratch (device globals; no allocations) ----------------
__device__ float g_q[MTOK * HIDK];
__device__ float g_k[MTOK * HIDK];
__device__ float g_v[MTOK * HIDK];
__device__ float g_xg[MTOK * HIDK];
__device__ float g_gk[MTOK * HIDK];
__device__ float g_att[MTOK * HIDK];
__device__ float g_expD[MTOK * HIDK];
__device__ float g_P[32 * NCH * HDIM * HDIM];
__device__ float g_S[32 * NCH * HDIM * HDIM];
// bf16 split operands
__device__ __align__(16) __nv_bfloat16 g_xh[MTOK * HIDK];
__device__ __align__(16) __nv_bfloat16 g_xl[MTOK * HIDK];
__device__ __align__(16) __nv_bfloat16 g_yh[MTOK * HIDK];
__device__ __align__(16) __nv_bfloat16 g_yl[MTOK * HIDK];
__device__ __align__(16) __nv_bfloat16 g_wh[5 * HIDK * HIDK];  // transposed [n][k]
__device__ __align__(16) __nv_bfloat16 g_wl[5 * HIDK * HIDK];

// ======================= helpers =======================
__device__ __forceinline__ uint32_t smem_u32(const void* p) {
    uint32_t a;
    asm("{ .reg .u64 t; cvta.to.shared.u64 t, %1; cvt.u32.u64 %0, t; }" : "=r"(a) : "l"(p));
    return a;
}
__device__ __forceinline__ void cpasync16(uint32_t s, const void* g) {
    asm volatile("cp.async.cg.shared.global [%0], [%1], 16;" ::"r"(s), "l"(g));
}
__device__ __forceinline__ void cpcommit() { asm volatile("cp.async.commit_group;"); }

__device__ __forceinline__ void ldmx4(uint32_t& r0, uint32_t& r1, uint32_t& r2,
                                      uint32_t& r3, uint32_t addr) {
    asm volatile("ldmatrix.sync.aligned.m8n8.x4.shared.b16 {%0,%1,%2,%3}, [%4];"
                 : "=r"(r0), "=r"(r1), "=r"(r2), "=r"(r3)
                 : "r"(addr));
}
__device__ __forceinline__ void mma16816(float* c, const uint32_t* a, const uint32_t* b) {
    asm volatile(
        "mma.sync.aligned.m16n8k16.row.col.f32.bf16.bf16.f32 "
        "{%0,%1,%2,%3}, {%4,%5,%6,%7}, {%8,%9}, {%0,%1,%2,%3};"
        : "+f"(c[0]), "+f"(c[1]), "+f"(c[2]), "+f"(c[3])
        : "r"(a[0]), "r"(a[1]), "r"(a[2]), "r"(a[3]), "r"(b[0]), "r"(b[1]));
}

// ======================= bf16 mma.sync GEMM (R4 version) =======================
// C[M,1024] = A(hi+lo)[M,1024] @ W(hi+lo)^T  via 3 split products.
// CTA tile 128x128, BK=32, 4-stage cp.async pipeline, 2 CTAs/SM.
#define ROWB 80       // 32 bf16 (64B) + 16B pad per row
#define STG_A (128 * ROWB)
#define STG (2 * STG_A)          // 20480 bytes per stage
#define NSTG 4
#define SMEM_MM (NSTG * STG)     // 81920 bytes
#define NSTAGES 96               // 3 phases * (1024/32)

__device__ __forceinline__ void mm_issue(int s, uint32_t sb, int tid, int brow, int bcol,
                                         const __nv_bfloat16* Ah, const __nv_bfloat16* Al,
                                         const __nv_bfloat16* Bh, const __nv_bfloat16* Bl) {
    if (s < NSTAGES) {
        int p = s >> 5;
        int kk = (s & 31) << 5;
        const __nv_bfloat16* Ab = (p < 2) ? Ah : Al;
        const __nv_bfloat16* Bb = (p == 1) ? Bl : Bh;
        uint32_t st = sb + (uint32_t)(s & 3) * STG;
        int row = tid >> 2, cw = tid & 3;
        const char* ga = (const char*)(Ab + (size_t)(brow + row) * HIDK + kk + cw * 8);
        cpasync16(st + row * ROWB + cw * 16, ga);
        cpasync16(st + (row + 64) * ROWB + cw * 16, ga + (size_t)64 * HIDK * 2);
        const char* gb = (const char*)(Bb + (size_t)(bcol + row) * HIDK + kk + cw * 8);
        cpasync16(st + STG_A + row * ROWB + cw * 16, gb);
        cpasync16(st + STG_A + (row + 64) * ROWB + cw * 16, gb + (size_t)64 * HIDK * 2);
    }
    cpcommit();  // empty groups at tail keep the pending-count invariant
}

__device__ __forceinline__ void mma_gemm_body(const __nv_bfloat16* __restrict__ Ah,
                                              const __nv_bfloat16* __restrict__ Al,
                                              const __nv_bfloat16* __restrict__ Bh,
                                              const __nv_bfloat16* __restrict__ Bl,
                                              float* __restrict__ C) {
    extern __shared__ char sm_raw[];
    uint32_t sb = smem_u32(sm_raw);
    int tid = threadIdx.x, lane = tid & 31, wid = tid >> 5;
    int wm = wid & 3, wn = wid >> 2;
    int brow = blockIdx.y * 128, bcol = blockIdx.x * 128;

    float c[2][8][4];
#pragma unroll
    for (int i = 0; i < 2; i++)
#pragma unroll
        for (int j = 0; j < 8; j++)
#pragma unroll
            for (int l = 0; l < 4; l++) c[i][j][l] = 0.f;

    mm_issue(0, sb, tid, brow, bcol, Ah, Al, Bh, Bl);
    mm_issue(1, sb, tid, brow, bcol, Ah, Al, Bh, Bl);
    mm_issue(2, sb, tid, brow, bcol, Ah, Al, Bh, Bl);

    int q = lane >> 3, r = lane & 7;

    for (int s = 0; s < NSTAGES; s++) {
        asm volatile("cp.async.wait_group 2;" ::: "memory");
        __syncthreads();
        uint32_t st = sb + (uint32_t)(s & 3) * STG;
        uint32_t sA = st, sB = st + STG_A;
#pragma unroll
        for (int k0 = 0; k0 < 32; k0 += 16) {
            uint32_t a[2][4], b[8][2];
#pragma unroll
            for (int mf = 0; mf < 2; mf++) {
                int rrow = wm * 32 + mf * 16 + (q & 1) * 8 + r;
                int kc = k0 + (q >> 1) * 8;
                ldmx4(a[mf][0], a[mf][1], a[mf][2], a[mf][3], sA + rrow * ROWB + kc * 2);
            }
#pragma unroll
            for (int pb = 0; pb < 4; pb++) {
                int nrow = wn * 64 + pb * 16 + (q >> 1) * 8 + r;
                int kc = k0 + (q & 1) * 8;
                uint32_t r0, r1, r2, r3;
                ldmx4(r0, r1, r2, r3, sB + nrow * ROWB + kc * 2);
                b[pb * 2][0] = r0;
                b[pb * 2][1] = r1;
                b[pb * 2 + 1][0] = r2;
                b[pb * 2 + 1][1] = r3;
            }
#pragma unroll
            for (int mf = 0; mf < 2; mf++)
#pragma unroll
                for (int nf = 0; nf < 8; nf++) mma16816(c[mf][nf], a[mf], b[nf]);
        }
        mm_issue(s + 3, sb, tid, brow, bcol, Ah, Al, Bh, Bl);
    }

    int qr = lane >> 2, qc = lane & 3;
#pragma unroll
    for (int mf = 0; mf < 2; mf++)
#pragma unroll
        for (int nf = 0; nf < 8; nf++) {
            int row0 = brow + wm * 32 + mf * 16 + qr;
            int col = bcol + wn * 64 + nf * 8 + qc * 2;
            *(float2*)&C[(size_t)row0 * HIDK + col] = make_float2(c[mf][nf][0], c[mf][nf][1]);
            *(float2*)&C[(size_t)(row0 + 8) * HIDK + col] = make_float2(c[mf][nf][2], c[mf][nf][3]);
        }
}

__global__ void __launch_bounds__(256, 2) mmproj_kernel() {
    int z = blockIdx.z;
    const __nv_bfloat16* Bh = g_wh + (size_t)z * HIDK * HIDK;
    const __nv_bfloat16* Bl = g_wl + (size_t)z * HIDK * HIDK;
    float* C = (z == 0) ? g_q : (z == 1) ? g_k : (z == 2) ? g_v : g_xg;
    mma_gemm_body(g_xh, g_xl, Bh, Bl, C);
}
__global__ void __launch_bounds__(256, 2) mmout_kernel(float* __restrict__ out) {
    mma_gemm_body(g_yh, g_yl, g_wh + (size_t)4 * HIDK * HIDK,
                  g_wl + (size_t)4 * HIDK * HIDK, out);
}

// ======================= conversion kernels =======================
__global__ void __launch_bounds__(256) xconv_kernel(const float* __restrict__ x) {
    size_t i = (size_t)blockIdx.x * 256 + threadIdx.x;
    float4 v = ((const float4*)x)[i];
    __nv_bfloat16 h0 = __float2bfloat16(v.x), h1 = __float2bfloat16(v.y);
    __nv_bfloat16 h2 = __float2bfloat16(v.z), h3 = __float2bfloat16(v.w);
    __nv_bfloat162* ph = (__nv_bfloat162*)g_xh;
    __nv_bfloat162* pl = (__nv_bfloat162*)g_xl;
    ph[2 * i] = __nv_bfloat162(h0, h1);
    ph[2 * i + 1] = __nv_bfloat162(h2, h3);
    pl[2 * i] = __nv_bfloat162(__float2bfloat16(v.x - __bfloat162float(h0)),
                               __float2bfloat16(v.y - __bfloat162float(h1)));
    pl[2 * i + 1] = __nv_bfloat162(__float2bfloat16(v.z - __bfloat162float(h2)),
                                   __float2bfloat16(v.w - __bfloat162float(h3)));
}

// transpose + split: Wt[n][k] = W[k][n]
__global__ void __launch_bounds__(256) wconv_kernel(const float* __restrict__ W0,
                                                    const float* __restrict__ W1,
                                                    const float* __restrict__ W2,
                                                    const float* __restrict__ W3,
                                                    const float* __restrict__ W4) {
    int z = blockIdx.z;
    const float* W = (z == 0) ? W0 : (z == 1) ? W1 : (z == 2) ? W2 : (z == 3) ? W3 : W4;
    __nv_bfloat16* Th = g_wh + (size_t)z * HIDK * HIDK;
    __nv_bfloat16* Tl = g_wl + (size_t)z * HIDK * HIDK;
    __shared__ float t[32][33];
    int n0 = blockIdx.x * 32, k0 = blockIdx.y * 32;
    int lx = threadIdx.x & 31, ly = threadIdx.x >> 5;
#pragma unroll
    for (int i = 0; i < 4; i++) {
        int r = ly + i * 8;
        t[r][lx] = W[(size_t)(k0 + r) * HIDK + n0 + lx];
    }
    __syncthreads();
#pragma unroll
    for (int i = 0; i < 4; i++) {
        int r = ly + i * 8;
        float v = t[lx][r];  // = W[k0+lx][n0+r]
        __nv_bfloat16 h = __float2bfloat16(v);
        size_t o = (size_t)(n0 + r) * HIDK + k0 + lx;
        Th[o] = h;
        Tl[o] = __float2bfloat16(v - __bfloat162float(h));
    }
}

// ---------------- fused low-rank gate path ---------------------------------
// One block = 16 tokens. W1 (1024x16) and W2 (16x1024) staged in 128KB smem.
#define SMEM_LR (32 * 1024 * sizeof(float))
__global__ void __launch_bounds__(256) lr_fused_kernel(const float* __restrict__ x,
                                                       const float* __restrict__ W1,
                                                       const float* __restrict__ W2,
                                                       const float* __restrict__ bias) {
    extern __shared__ float s[];
    float* w1s = s;            // [1024*16]
    float* w2s = s + 16384;    // [16*1024]
    __shared__ float ts[16][17];
    int tid = threadIdx.x;
#pragma unroll
    for (int i = 0; i < 16; i++) {
        int idx = tid + i * 256;  // 4096 float4 each
        ((float4*)w1s)[idx] = ((const float4*)W1)[idx];
        ((float4*)w2s)[idx] = ((const float4*)W2)[idx];
    }
    __syncthreads();

    int m0 = blockIdx.x * 16;
    // phase 1: t[m][r] = x[m] . W1[:,r]
    {
        int mt = tid >> 4, r = tid & 15;
        const float* xr = x + (size_t)(m0 + mt) * HIDK;
        float acc = 0.f;
#pragma unroll 8
        for (int kk = 0; kk < HIDK; kk++) acc = fmaf(xr[kk], w1s[kk * 16 + r], acc);
        ts[mt][r] = acc;
    }
    __syncthreads();

    // phase 2: gk[m][n] = log_sigmoid(t[m] . W2[:,n] + b[n]) / 16
    int n = tid * 4;
    float4 b4 = *(const float4*)(bias + n);
#pragma unroll 1
    for (int mi = 0; mi < 16; mi++) {
        float4 a = b4;
#pragma unroll
        for (int rr = 0; rr < 16; rr++) {
            float tv = ts[mi][rr];
            float4 w = *(float4*)&w2s[rr * 1024 + n];
            a.x = fmaf(tv, w.x, a.x);
            a.y = fmaf(tv, w.y, a.y);
            a.z = fmaf(tv, w.z, a.z);
            a.w = fmaf(tv, w.w, a.w);
        }
        float4 o;
        o.x = (fminf(a.x, 0.f) - __logf(1.f + __expf(-fabsf(a.x)))) * 0.0625f;
        o.y = (fminf(a.y, 0.f) - __logf(1.f + __expf(-fabsf(a.y)))) * 0.0625f;
        o.z = (fminf(a.z, 0.f) - __logf(1.f + __expf(-fabsf(a.z)))) * 0.0625f;
        o.w = (fminf(a.w, 0.f) - __logf(1.f + __expf(-fabsf(a.w)))) * 0.0625f;
        *(float4*)(g_gk + (size_t)(m0 + mi) * HIDK + n) = o;
    }
}

// ---------------- chunked GLA: kernel A (intra-chunk + summaries) ----------
__global__ void __launch_bounds__(256) chunk_kernel() {
    extern __shared__ float sm[];
    float* sQt = sm;
    float* sKt = sm + 64 * PD;
    float* sK = sm + 2 * 64 * PD;
    float* sU = sm + 3 * 64 * PD;
    float* sAV = sm + 4 * 64 * PD;
    float* sED = sm + 5 * 64 * PD;
    __shared__ float sTot[4][64];

    int c = blockIdx.x, bh = blockIdx.y;
    int b = bh >> 4, h = bh & 15;
    int tid = threadIdx.x;
    size_t rowbase = (size_t)(b * LSEQ + c * CT) * HIDK + h * HDIM;

#pragma unroll
    for (int i = 0; i < 4; i++) {
        int idx = tid + i * 256;
        int t = idx >> 4, c4 = (idx & 15) << 2;
        size_t gi = rowbase + (size_t)t * HIDK + c4;
        float4 q4 = *(const float4*)(g_q + gi);
        float4 k4 = *(const float4*)(g_k + gi);
        float4 v4 = *(const float4*)(g_v + gi);
        float4 gg = *(const float4*)(g_gk + gi);
        sQt[(c4 + 0) * PD + t] = q4.x;
        sQt[(c4 + 1) * PD + t] = q4.y;
        sQt[(c4 + 2) * PD + t] = q4.z;
        sQt[(c4 + 3) * PD + t] = q4.w;
        sKt[(c4 + 0) * PD + t] = k4.x;
        sKt[(c4 + 1) * PD + t] = k4.y;
        sKt[(c4 + 2) * PD + t] = k4.z;
        sKt[(c4 + 3) * PD + t] = k4.w;
        *(float4*)&sK[t * PD + c4] = k4;
        *(float4*)&sAV[t * PD + c4] = v4;
        *(float4*)&sED[t * PD + c4] = gg;
    }
    __syncthreads();

    // segment-parallel cumsum over t (64 channels x 4 segments of 16)
    {
        int ch = tid & 63, seg = tid >> 6;
        int t0s = seg * 16;
        float run = 0.f;
#pragma unroll
        for (int t = t0s; t < t0s + 16; t++) {
            run += sED[t * PD + ch];
            sED[t * PD + ch] = run;
        }
        sTot[seg][ch] = run;
    }
    __syncthreads();
    {
        int ch = tid & 63, seg = tid >> 6;
        float off = 0.f;
        if (seg > 0) off += sTot[0][ch];
        if (seg > 1) off += sTot[1][ch];
        if (seg > 2) off += sTot[2][ch];
        int t0s = seg * 16;
#pragma unroll
        for (int t = t0s; t < t0s + 16; t++) {
            float D = sED[t * PD + ch] + off;
            sED[t * PD + ch] = __expf(D);
            sU[t * PD + ch] = __expf(-D) * sAV[t * PD + ch];
        }
    }
    __syncthreads();

#pragma unroll
    for (int i = 0; i < 4; i++) {
        int idx = tid + i * 256;
        int t = idx >> 4, c4 = (idx & 15) << 2;
        *(float4*)(g_expD + rowbase + (size_t)t * HIDK + c4) = *(float4*)&sED[t * PD + c4];
    }

    {
        int t0 = (tid & 15) << 2, s0 = (tid >> 4) << 2;
        float acc[4][4];
#pragma unroll
        for (int i = 0; i < 4; i++)
#pragma unroll
            for (int j = 0; j < 4; j++) acc[i][j] = 0.f;
        for (int d = 0; d < 64; d++) {
            float4 a = *(float4*)&sQt[d * PD + t0];
            float4 bb = *(float4*)&sKt[d * PD + s0];
            float av[4] = {a.x, a.y, a.z, a.w};
            float bv[4] = {bb.x, bb.y, bb.z, bb.w};
#pragma unroll
            for (int i = 0; i < 4; i++)
#pragma unroll
                for (int j = 0; j < 4; j++) acc[i][j] = fmaf(av[i], bv[j], acc[i][j]);
        }
#pragma unroll
        for (int j = 0; j < 4; j++) {
            int s = s0 + j;
            float4 o;
            o.x = (s <= t0 + 0) ? acc[0][j] : 0.f;
            o.y = (s <= t0 + 1) ? acc[1][j] : 0.f;
            o.z = (s <= t0 + 2) ? acc[2][j] : 0.f;
            o.w = (s <= t0 + 3) ? acc[3][j] : 0.f;
            *(float4*)&sAV[s * PD + t0] = o;
        }
    }
    __syncthreads();

    int r0 = (tid >> 4) << 2, c0 = (tid & 15) << 2;

    {
        float acc[4][4];
#pragma unroll
        for (int i = 0; i < 4; i++)
#pragma unroll
            for (int j = 0; j < 4; j++) acc[i][j] = 0.f;
        for (int s = 0; s < CT; s++) {
            float4 a = *(float4*)&sAV[s * PD + r0];
            float4 bb = *(float4*)&sU[s * PD + c0];
            float av[4] = {a.x, a.y, a.z, a.w};
            float bv[4] = {bb.x, bb.y, bb.z, bb.w};
#pragma unroll
            for (int i = 0; i < 4; i++)
#pragma unroll
                for (int j = 0; j < 4; j++) acc[i][j] = fmaf(av[i], bv[j], acc[i][j]);
        }
#pragma unroll
        for (int i = 0; i < 4; i++) {
            int t = r0 + i;
            float4 e = *(float4*)&sED[t * PD + c0];
            float4 o = make_float4(acc[i][0] * e.x, acc[i][1] * e.y, acc[i][2] * e.z,
                                   acc[i][3] * e.w);
            *(float4*)(g_att + rowbase + (size_t)t * HIDK + c0) = o;
        }
    }

    {
        float acc[4][4];
#pragma unroll
        for (int i = 0; i < 4; i++)
#pragma unroll
            for (int j = 0; j < 4; j++) acc[i][j] = 0.f;
        for (int s = 0; s < CT; s++) {
            float4 a = *(float4*)&sU[s * PD + r0];
            float4 bb = *(float4*)&sK[s * PD + c0];
            float av[4] = {a.x, a.y, a.z, a.w};
            float bv[4] = {bb.x, bb.y, bb.z, bb.w};
#pragma unroll
            for (int i = 0; i < 4; i++)
#pragma unroll
                for (int j = 0; j < 4; j++) acc[i][j] = fmaf(av[i], bv[j], acc[i][j]);
        }
        size_t pbase = ((size_t)(bh * NCH + c)) << 12;
#pragma unroll
        for (int i = 0; i < 4; i++) {
            float ev = sED[63 * PD + r0 + i];
            float4 o = make_float4(acc[i][0] * ev, acc[i][1] * ev, acc[i][2] * ev,
                                   acc[i][3] * ev);
            *(float4*)(g_P + pbase + ((size_t)(r0 + i) << 6) + c0) = o;
        }
    }
}

// ---------------- kernel B: scan over chunk states --------------------------
__global__ void __launch_bounds__(512) chunkscan_kernel() {
    int bh = blockIdx.x;
    int b = bh >> 4, h = bh & 15;
    int tid = threadIdx.x;
    int v = tid >> 3;
    int k0 = (tid & 7) << 3;
    float S[8];
#pragma unroll
    for (int j = 0; j < 8; j++) S[j] = 0.f;

    for (int c = 0; c < NCH; c++) {
        size_t base = (((size_t)(bh * NCH + c)) << 12) + ((size_t)v << 6) + k0;
        *(float4*)(g_S + base) = make_float4(S[0], S[1], S[2], S[3]);
        *(float4*)(g_S + base + 4) = make_float4(S[4], S[5], S[6], S[7]);
        float E = g_expD[((size_t)(b * LSEQ + c * CT + 63)) * HIDK + h * HDIM + v];
        float4 p0 = *(float4*)(g_P + base);
        float4 p1 = *(float4*)(g_P + base + 4);
        S[0] = fmaf(S[0], E, p0.x);
        S[1] = fmaf(S[1], E, p0.y);
        S[2] = fmaf(S[2], E, p0.z);
        S[3] = fmaf(S[3], E, p0.w);
        S[4] = fmaf(S[4], E, p1.x);
        S[5] = fmaf(S[5], E, p1.y);
        S[6] = fmaf(S[6], E, p1.z);
        S[7] = fmaf(S[7], E, p1.w);
    }
}

// ---------------- kernel C: inter-chunk output ------------------------------
__global__ void __launch_bounds__(256) inter_kernel() {
    __shared__ float sQt[64 * PD];
    __shared__ float sSt[64 * PD];
    int c = blockIdx.x, bh = blockIdx.y;
    int b = bh >> 4, h = bh & 15;
    int tid = threadIdx.x;
    size_t rowbase = (size_t)(b * LSEQ + c * CT) * HIDK + h * HDIM;
    size_t sbase = ((size_t)(bh * NCH + c)) << 12;

#pragma unroll
    for (int i = 0; i < 4; i++) {
        int idx = tid + i * 256;
        int t = idx >> 4, c4 = (idx & 15) << 2;
        float4 q4 = *(const float4*)(g_q + rowbase + (size_t)t * HIDK + c4);
        sQt[(c4 + 0) * PD + t] = q4.x;
        sQt[(c4 + 1) * PD + t] = q4.y;
        sQt[(c4 + 2) * PD + t] = q4.z;
        sQt[(c4 + 3) * PD + t] = q4.w;
        float4 s4 = *(const float4*)(g_S + sbase + ((size_t)t << 6) + c4);
        sSt[(c4 + 0) * PD + t] = s4.x;
        sSt[(c4 + 1) * PD + t] = s4.y;
        sSt[(c4 + 2) * PD + t] = s4.z;
        sSt[(c4 + 3) * PD + t] = s4.w;
    }
    __syncthreads();

    int t0 = (tid >> 4) << 2, v0 = (tid & 15) << 2;
    float acc[4][4];
#pragma unroll
    for (int i = 0; i < 4; i++)
#pragma unroll
        for (int j = 0; j < 4; j++) acc[i][j] = 0.f;
    for (int k = 0; k < 64; k++) {
        float4 a = *(float4*)&sQt[k * PD + t0];
        float4 bb = *(float4*)&sSt[k * PD + v0];
        float av[4] = {a.x, a.y, a.z, a.w};
        float bv[4] = {bb.x, bb.y, bb.z, bb.w};
#pragma unroll
        for (int i = 0; i < 4; i++)
#pragma unroll
            for (int j = 0; j < 4; j++) acc[i][j] = fmaf(av[i], bv[j], acc[i][j]);
    }
#pragma unroll
    for (int i = 0; i < 4; i++) {
        int t = t0 + i;
        size_t gi = rowbase + (size_t)t * HIDK + v0;
        float4 e = *(float4*)(g_expD + gi);
        float4 o = *(float4*)(g_att + gi);
        o.x = fmaf(acc[i][0], e.x, o.x);
        o.y = fmaf(acc[i][1], e.y, o.y);
        o.z = fmaf(acc[i][2], e.z, o.z);
        o.w = fmaf(acc[i][3], e.w, o.w);
        *(float4*)(g_att + gi) = o;
    }
}

// ---------------- LayerNorm + SiLU gate -> bf16-split y ---------------------
__global__ void __launch_bounds__(256) ln_gate_kernel(const float* __restrict__ gamma,
                                                      const float* __restrict__ beta) {
    int row = blockIdx.x;
    int tid = threadIdx.x;
    const float* a = g_att + (size_t)row * HIDK;
    float vals[4];
    float s = 0.f, s2 = 0.f;
#pragma unroll
    for (int i = 0; i < 4; i++) {
        vals[i] = a[i * 256 + tid];
        s += vals[i];
        s2 = fmaf(vals[i], vals[i], s2);
    }
#pragma unroll
    for (int o = 16; o; o >>= 1) {
        s += __shfl_xor_sync(0xffffffffu, s, o);
        s2 += __shfl_xor_sync(0xffffffffu, s2, o);
    }
    __shared__ float rs[8], rs2[8];
    int warp = tid >> 5;
    if ((tid & 31) == 0) { rs[warp] = s; rs2[warp] = s2; }
    __syncthreads();
    s = 0.f;
    s2 = 0.f;
#pragma unroll
    for (int w = 0; w < 8; w++) { s += rs[w]; s2 += rs2[w]; }
    float mean = s * (1.f / HIDK);
    float var = s2 * (1.f / HIDK) - mean * mean;
    float rstd = rsqrtf(var + 1e-5f);
#pragma unroll
    for (int i = 0; i < 4; i++) {
        int col = i * 256 + tid;
        float gv = g_xg[(size_t)row * HIDK + col];
        float sil = gv / (1.f + __expf(-gv));
        float yv = ((vals[i] - mean) * rstd * gamma[col] + beta[col]) * sil;
        __nv_bfloat16 h = __float2bfloat16(yv);
        g_yh[(size_t)row * HIDK + col] = h;
        g_yl[(size_t)row * HIDK + col] = __float2bfloat16(yv - __bfloat162float(h));
    }
}

// ---------------- launch --------------------------------------------------
extern "C" void kernel_launch(void* const* d_in, const int* in_sizes, int n_in,
                              void* d_out, int out_size) {
    const float* x = (const float*)d_in[0];
    const float* Wq = (const float*)d_in[1];
    const float* Wk = (const float*)d_in[2];
    const float* Wv = (const float*)d_in[3];
    const float* Wg = (const float*)d_in[4];
    const float* Wgk1 = (const float*)d_in[5];
    const float* Wgk2 = (const float*)d_in[6];
    const float* bgk2 = (const float*)d_in[7];
    const float* gamma = (const float*)d_in[8];
    const float* beta = (const float*)d_in[9];
    const float* Wout = (const float*)d_in[10];
    float* out = (float*)d_out;

    const int SMEM_A = 6 * 64 * PD * sizeof(float);
    cudaFuncSetAttribute(chunk_kernel, cudaFuncAttributeMaxDynamicSharedMemorySize, SMEM_A);
    cudaFuncSetAttribute(mmproj_kernel, cudaFuncAttributeMaxDynamicSharedMemorySize, SMEM_MM);
    cudaFuncSetAttribute(mmout_kernel, cudaFuncAttributeMaxDynamicSharedMemorySize, SMEM_MM);
    cudaFuncSetAttribute(lr_fused_kernel, cudaFuncAttributeMaxDynamicSharedMemorySize, SMEM_LR);

    xconv_kernel<<<MTOK * HIDK / 1024, 256>>>(x);
    wconv_kernel<<<dim3(32, 32, 5), 256>>>(Wq, Wk, Wv, Wg, Wout);
    lr_fused_kernel<<<MTOK / 16, 256, SMEM_LR>>>(x, Wgk1, Wgk2, bgk2);

    mmproj_kernel<<<dim3(8, 32, 4), 256, SMEM_MM>>>();

    chunk_kernel<<<dim3(NCH, 32), 256, SMEM_A>>>();
    chunkscan_kernel<<<32, 512>>>();
    inter_kernel<<<dim3(NCH, 32), 256>>>();
    ln_gate_kernel<<<MTOK, 256>>>(gamma, beta);

    mmout_kernel<<<dim3(8, 32, 1), 256, SMEM_MM>>>(out);
}

// round 7
// speedup vs baseline: 1.4367x; 1.2528x over previous
#include <cuda_runtime.h>
#include <cuda_fp16.h>
#include <math.h>
#include <stdint.h>

#define HIDK 1024
#define MTOK 4096
#define LSEQ 2048
#define NHEAD 16
#define HDIM 64
#define CT 64
#define NCH (LSEQ / CT)
#define PD 68

// ---------------- scratch (device globals; no allocations) ----------------
__device__ float g_q[MTOK * HIDK];
__device__ float g_k[MTOK * HIDK];
__device__ float g_v[MTOK * HIDK];
__device__ float g_xg[MTOK * HIDK];
__device__ float g_gk[MTOK * HIDK];
__device__ float g_att[MTOK * HIDK];
__device__ float g_expD[MTOK * HIDK];
__device__ float g_P[32 * NCH * HDIM * HDIM];
__device__ float g_S[32 * NCH * HDIM * HDIM];
// fp16 operands: activations single + 2^-10-scaled copy; weights exact pair
__device__ __align__(16) __half g_xh[MTOK * HIDK];
__device__ __align__(16) __half g_xs[MTOK * HIDK];   // x * 2^-10
__device__ __align__(16) __half g_yh[MTOK * HIDK];
__device__ __align__(16) __half g_ys[MTOK * HIDK];   // y * 2^-10
__device__ __align__(16) __half g_wh[5 * HIDK * HIDK];  // transposed [n][k], round(W)
__device__ __align__(16) __half g_wl[5 * HIDK * HIDK];  // (W - Wh) * 2^10

// ======================= helpers =======================
__device__ __forceinline__ uint32_t smem_u32(const void* p) {
    uint32_t a;
    asm("{ .reg .u64 t; cvta.to.shared.u64 t, %1; cvt.u32.u64 %0, t; }" : "=r"(a) : "l"(p));
    return a;
}
__device__ __forceinline__ void cpasync16(uint32_t s, const void* g) {
    asm volatile("cp.async.cg.shared.global [%0], [%1], 16;" ::"r"(s), "l"(g));
}
__device__ __forceinline__ void cpcommit() { asm volatile("cp.async.commit_group;"); }

__device__ __forceinline__ void ldmx4(uint32_t& r0, uint32_t& r1, uint32_t& r2,
                                      uint32_t& r3, uint32_t addr) {
    asm volatile("ldmatrix.sync.aligned.m8n8.x4.shared.b16 {%0,%1,%2,%3}, [%4];"
                 : "=r"(r0), "=r"(r1), "=r"(r2), "=r"(r3)
                 : "r"(addr));
}
__device__ __forceinline__ void mma16816(float* c, const uint32_t* a, const uint32_t* b) {
    asm volatile(
        "mma.sync.aligned.m16n8k16.row.col.f32.f16.f16.f32 "
        "{%0,%1,%2,%3}, {%4,%5,%6,%7}, {%8,%9}, {%0,%1,%2,%3};"
        : "+f"(c[0]), "+f"(c[1]), "+f"(c[2]), "+f"(c[3])
        : "r"(a[0]), "r"(a[1]), "r"(a[2]), "r"(a[3]), "r"(b[0]), "r"(b[1]));
}

// ======================= fp16 mma.sync GEMM =======================
// C[M,1024] = X @ Wh^T + (X*2^-10) @ (Wl*2^10)^T  (2 split products).
// CTA tile 128x128, BK=32, 4-stage cp.async pipeline, 2 CTAs/SM.
#define ROWB 80       // 32 fp16 (64B) + 16B pad per row
#define STG_A (128 * ROWB)
#define STG (2 * STG_A)          // 20480 bytes per stage
#define NSTG 4
#define SMEM_MM (NSTG * STG)     // 81920 bytes
#define NSTAGES 64               // 2 phases * (1024/32)

__device__ __forceinline__ void mm_issue(int s, uint32_t sb, int tid, int brow, int bcol,
                                         const __half* Ah, const __half* As,
                                         const __half* Bh, const __half* Bl) {
    if (s < NSTAGES) {
        int p = s >> 5;
        int kk = (s & 31) << 5;
        const __half* Ab = p ? As : Ah;
        const __half* Bb = p ? Bl : Bh;
        uint32_t st = sb + (uint32_t)(s & 3) * STG;
        int row = tid >> 2, cw = tid & 3;
        const char* ga = (const char*)(Ab + (size_t)(brow + row) * HIDK + kk + cw * 8);
        cpasync16(st + row * ROWB + cw * 16, ga);
        cpasync16(st + (row + 64) * ROWB + cw * 16, ga + (size_t)64 * HIDK * 2);
        const char* gb = (const char*)(Bb + (size_t)(bcol + row) * HIDK + kk + cw * 8);
        cpasync16(st + STG_A + row * ROWB + cw * 16, gb);
        cpasync16(st + STG_A + (row + 64) * ROWB + cw * 16, gb + (size_t)64 * HIDK * 2);
    }
    cpcommit();  // empty groups at tail keep the pending-count invariant
}

__device__ __forceinline__ void mma_gemm_body(const __half* __restrict__ Ah,
                                              const __half* __restrict__ As,
                                              const __half* __restrict__ Bh,
                                              const __half* __restrict__ Bl,
                                              float* __restrict__ C) {
    extern __shared__ char sm_raw[];
    uint32_t sb = smem_u32(sm_raw);
    int tid = threadIdx.x, lane = tid & 31, wid = tid >> 5;
    int wm = wid & 3, wn = wid >> 2;
    int brow = blockIdx.y * 128, bcol = blockIdx.x * 128;

    float c[2][8][4];
#pragma unroll
    for (int i = 0; i < 2; i++)
#pragma unroll
        for (int j = 0; j < 8; j++)
#pragma unroll
            for (int l = 0; l < 4; l++) c[i][j][l] = 0.f;

    mm_issue(0, sb, tid, brow, bcol, Ah, As, Bh, Bl);
    mm_issue(1, sb, tid, brow, bcol, Ah, As, Bh, Bl);
    mm_issue(2, sb, tid, brow, bcol, Ah, As, Bh, Bl);

    int q = lane >> 3, r = lane & 7;

    for (int s = 0; s < NSTAGES; s++) {
        asm volatile("cp.async.wait_group 2;" ::: "memory");
        __syncthreads();
        uint32_t st = sb + (uint32_t)(s & 3) * STG;
        uint32_t sA = st, sB = st + STG_A;
#pragma unroll
        for (int k0 = 0; k0 < 32; k0 += 16) {
            uint32_t a[2][4], b[8][2];
#pragma unroll
            for (int mf = 0; mf < 2; mf++) {
                int rrow = wm * 32 + mf * 16 + (q & 1) * 8 + r;
                int kc = k0 + (q >> 1) * 8;
                ldmx4(a[mf][0], a[mf][1], a[mf][2], a[mf][3], sA + rrow * ROWB + kc * 2);
            }
#pragma unroll
            for (int pb = 0; pb < 4; pb++) {
                int nrow = wn * 64 + pb * 16 + (q >> 1) * 8 + r;
                int kc = k0 + (q & 1) * 8;
                uint32_t r0, r1, r2, r3;
                ldmx4(r0, r1, r2, r3, sB + nrow * ROWB + kc * 2);
                b[pb * 2][0] = r0;
                b[pb * 2][1] = r1;
                b[pb * 2 + 1][0] = r2;
                b[pb * 2 + 1][1] = r3;
            }
#pragma unroll
            for (int mf = 0; mf < 2; mf++)
#pragma unroll
                for (int nf = 0; nf < 8; nf++) mma16816(c[mf][nf], a[mf], b[nf]);
        }
        mm_issue(s + 3, sb, tid, brow, bcol, Ah, As, Bh, Bl);
    }

    int qr = lane >> 2, qc = lane & 3;
#pragma unroll
    for (int mf = 0; mf < 2; mf++)
#pragma unroll
        for (int nf = 0; nf < 8; nf++) {
            int row0 = brow + wm * 32 + mf * 16 + qr;
            int col = bcol + wn * 64 + nf * 8 + qc * 2;
            *(float2*)&C[(size_t)row0 * HIDK + col] = make_float2(c[mf][nf][0], c[mf][nf][1]);
            *(float2*)&C[(size_t)(row0 + 8) * HIDK + col] = make_float2(c[mf][nf][2], c[mf][nf][3]);
        }
}

__global__ void __launch_bounds__(256, 2) mmproj_kernel() {
    int z = blockIdx.z;
    const __half* Bh = g_wh + (size_t)z * HIDK * HIDK;
    const __half* Bl = g_wl + (size_t)z * HIDK * HIDK;
    float* C = (z == 0) ? g_q : (z == 1) ? g_k : (z == 2) ? g_v : g_xg;
    mma_gemm_body(g_xh, g_xs, Bh, Bl, C);
}
__global__ void __launch_bounds__(256, 2) mmout_kernel(float* __restrict__ out) {
    mma_gemm_body(g_yh, g_ys, g_wh + (size_t)4 * HIDK * HIDK,
                  g_wl + (size_t)4 * HIDK * HIDK, out);
}

// ======================= conversion kernels =======================
#define SC_DN (1.f / 1024.f)
__global__ void __launch_bounds__(256) xconv_kernel(const float* __restrict__ x) {
    size_t i = (size_t)blockIdx.x * 256 + threadIdx.x;
    float4 v = ((const float4*)x)[i];
    __half2* ph = (__half2*)g_xh;
    __half2* ps = (__half2*)g_xs;
    ph[2 * i] = __halves2half2(__float2half(v.x), __float2half(v.y));
    ph[2 * i + 1] = __halves2half2(__float2half(v.z), __float2half(v.w));
    ps[2 * i] = __halves2half2(__float2half(v.x * SC_DN), __float2half(v.y * SC_DN));
    ps[2 * i + 1] = __halves2half2(__float2half(v.z * SC_DN), __float2half(v.w * SC_DN));
}

// transpose + split: Wh[n][k] = round(W[k][n]); Wl[n][k] = (W - Wh) * 2^10
__global__ void __launch_bounds__(256) wconv_kernel(const float* __restrict__ W0,
                                                    const float* __restrict__ W1,
                                                    const float* __restrict__ W2,
                                                    const float* __restrict__ W3,
                                                    const float* __restrict__ W4) {
    int z = blockIdx.z;
    const float* W = (z == 0) ? W0 : (z == 1) ? W1 : (z == 2) ? W2 : (z == 3) ? W3 : W4;
    __half* Th = g_wh + (size_t)z * HIDK * HIDK;
    __half* Tl = g_wl + (size_t)z * HIDK * HIDK;
    __shared__ float t[32][33];
    int n0 = blockIdx.x * 32, k0 = blockIdx.y * 32;
    int lx = threadIdx.x & 31, ly = threadIdx.x >> 5;
#pragma unroll
    for (int i = 0; i < 4; i++) {
        int r = ly + i * 8;
        t[r][lx] = W[(size_t)(k0 + r) * HIDK + n0 + lx];
    }
    __syncthreads();
#pragma unroll
    for (int i = 0; i < 4; i++) {
        int r = ly + i * 8;
        float v = t[lx][r];  // = W[k0+lx][n0+r]
        __half h = __float2half(v);
        size_t o = (size_t)(n0 + r) * HIDK + k0 + lx;
        Th[o] = h;
        Tl[o] = __float2half((v - __half2float(h)) * 1024.f);
    }
}

// ---------------- fused low-rank gate path ---------------------------------
#define SMEM_LR (32 * 1024 * sizeof(float))
__global__ void __launch_bounds__(256) lr_fused_kernel(const float* __restrict__ x,
                                                       const float* __restrict__ W1,
                                                       const float* __restrict__ W2,
                                                       const float* __restrict__ bias) {
    extern __shared__ float s[];
    float* w1s = s;            // [1024*16]
    float* w2s = s + 16384;    // [16*1024]
    __shared__ float ts[16][17];
    int tid = threadIdx.x;
#pragma unroll
    for (int i = 0; i < 16; i++) {
        int idx = tid + i * 256;  // 4096 float4 each
        ((float4*)w1s)[idx] = ((const float4*)W1)[idx];
        ((float4*)w2s)[idx] = ((const float4*)W2)[idx];
    }
    __syncthreads();

    int m0 = blockIdx.x * 16;
    {
        int mt = tid >> 4, r = tid & 15;
        const float* xr = x + (size_t)(m0 + mt) * HIDK;
        float acc = 0.f;
#pragma unroll 8
        for (int kk = 0; kk < HIDK; kk++) acc = fmaf(xr[kk], w1s[kk * 16 + r], acc);
        ts[mt][r] = acc;
    }
    __syncthreads();

    int n = tid * 4;
    float4 b4 = *(const float4*)(bias + n);
#pragma unroll 1
    for (int mi = 0; mi < 16; mi++) {
        float4 a = b4;
#pragma unroll
        for (int rr = 0; rr < 16; rr++) {
            float tv = ts[mi][rr];
            float4 w = *(float4*)&w2s[rr * 1024 + n];
            a.x = fmaf(tv, w.x, a.x);
            a.y = fmaf(tv, w.y, a.y);
            a.z = fmaf(tv, w.z, a.z);
            a.w = fmaf(tv, w.w, a.w);
        }
        float4 o;
        o.x = (fminf(a.x, 0.f) - __logf(1.f + __expf(-fabsf(a.x)))) * 0.0625f;
        o.y = (fminf(a.y, 0.f) - __logf(1.f + __expf(-fabsf(a.y)))) * 0.0625f;
        o.z = (fminf(a.z, 0.f) - __logf(1.f + __expf(-fabsf(a.z)))) * 0.0625f;
        o.w = (fminf(a.w, 0.f) - __logf(1.f + __expf(-fabsf(a.w)))) * 0.0625f;
        *(float4*)(g_gk + (size_t)(m0 + mi) * HIDK + n) = o;
    }
}

// ---------------- chunked GLA: kernel A (intra-chunk + summaries) ----------
__global__ void __launch_bounds__(256) chunk_kernel() {
    extern __shared__ float sm[];
    float* sQt = sm;
    float* sKt = sm + 64 * PD;
    float* sK = sm + 2 * 64 * PD;
    float* sU = sm + 3 * 64 * PD;
    float* sAV = sm + 4 * 64 * PD;
    float* sED = sm + 5 * 64 * PD;
    __shared__ float sTot[4][64];

    int c = blockIdx.x, bh = blockIdx.y;
    int b = bh >> 4, h = bh & 15;
    int tid = threadIdx.x;
    size_t rowbase = (size_t)(b * LSEQ + c * CT) * HIDK + h * HDIM;

#pragma unroll
    for (int i = 0; i < 4; i++) {
        int idx = tid + i * 256;
        int t = idx >> 4, c4 = (idx & 15) << 2;
        size_t gi = rowbase + (size_t)t * HIDK + c4;
        float4 q4 = *(const float4*)(g_q + gi);
        float4 k4 = *(const float4*)(g_k + gi);
        float4 v4 = *(const float4*)(g_v + gi);
        float4 gg = *(const float4*)(g_gk + gi);
        sQt[(c4 + 0) * PD + t] = q4.x;
        sQt[(c4 + 1) * PD + t] = q4.y;
        sQt[(c4 + 2) * PD + t] = q4.z;
        sQt[(c4 + 3) * PD + t] = q4.w;
        sKt[(c4 + 0) * PD + t] = k4.x;
        sKt[(c4 + 1) * PD + t] = k4.y;
        sKt[(c4 + 2) * PD + t] = k4.z;
        sKt[(c4 + 3) * PD + t] = k4.w;
        *(float4*)&sK[t * PD + c4] = k4;
        *(float4*)&sAV[t * PD + c4] = v4;
        *(float4*)&sED[t * PD + c4] = gg;
    }
    __syncthreads();

    // segment-parallel cumsum over t (64 channels x 4 segments of 16)
    {
        int ch = tid & 63, seg = tid >> 6;
        int t0s = seg * 16;
        float run = 0.f;
#pragma unroll
        for (int t = t0s; t < t0s + 16; t++) {
            run += sED[t * PD + ch];
            sED[t * PD + ch] = run;
        }
        sTot[seg][ch] = run;
    }
    __syncthreads();
    {
        int ch = tid & 63, seg = tid >> 6;
        float off = 0.f;
        if (seg > 0) off += sTot[0][ch];
        if (seg > 1) off += sTot[1][ch];
        if (seg > 2) off += sTot[2][ch];
        int t0s = seg * 16;
#pragma unroll
        for (int t = t0s; t < t0s + 16; t++) {
            float D = sED[t * PD + ch] + off;
            sED[t * PD + ch] = __expf(D);
            sU[t * PD + ch] = __expf(-D) * sAV[t * PD + ch];
        }
    }
    __syncthreads();

#pragma unroll
    for (int i = 0; i < 4; i++) {
        int idx = tid + i * 256;
        int t = idx >> 4, c4 = (idx & 15) << 2;
        *(float4*)(g_expD + rowbase + (size_t)t * HIDK + c4) = *(float4*)&sED[t * PD + c4];
    }

    {
        int t0 = (tid & 15) << 2, s0 = (tid >> 4) << 2;
        float acc[4][4];
#pragma unroll
        for (int i = 0; i < 4; i++)
#pragma unroll
            for (int j = 0; j < 4; j++) acc[i][j] = 0.f;
        for (int d = 0; d < 64; d++) {
            float4 a = *(float4*)&sQt[d * PD + t0];
            float4 bb = *(float4*)&sKt[d * PD + s0];
            float av[4] = {a.x, a.y, a.z, a.w};
            float bv[4] = {bb.x, bb.y, bb.z, bb.w};
#pragma unroll
            for (int i = 0; i < 4; i++)
#pragma unroll
                for (int j = 0; j < 4; j++) acc[i][j] = fmaf(av[i], bv[j], acc[i][j]);
        }
#pragma unroll
        for (int j = 0; j < 4; j++) {
            int s = s0 + j;
            float4 o;
            o.x = (s <= t0 + 0) ? acc[0][j] : 0.f;
            o.y = (s <= t0 + 1) ? acc[1][j] : 0.f;
            o.z = (s <= t0 + 2) ? acc[2][j] : 0.f;
            o.w = (s <= t0 + 3) ? acc[3][j] : 0.f;
            *(float4*)&sAV[s * PD + t0] = o;
        }
    }
    __syncthreads();

    int r0 = (tid >> 4) << 2, c0 = (tid & 15) << 2;

    {
        float acc[4][4];
#pragma unroll
        for (int i = 0; i < 4; i++)
#pragma unroll
            for (int j = 0; j < 4; j++) acc[i][j] = 0.f;
        for (int s = 0; s < CT; s++) {
            float4 a = *(float4*)&sAV[s * PD + r0];
            float4 bb = *(float4*)&sU[s * PD + c0];
            float av[4] = {a.x, a.y, a.z, a.w};
            float bv[4] = {bb.x, bb.y, bb.z, bb.w};
#pragma unroll
            for (int i = 0; i < 4; i++)
#pragma unroll
                for (int j = 0; j < 4; j++) acc[i][j] = fmaf(av[i], bv[j], acc[i][j]);
        }
#pragma unroll
        for (int i = 0; i < 4; i++) {
            int t = r0 + i;
            float4 e = *(float4*)&sED[t * PD + c0];
            float4 o = make_float4(acc[i][0] * e.x, acc[i][1] * e.y, acc[i][2] * e.z,
                                   acc[i][3] * e.w);
            *(float4*)(g_att + rowbase + (size_t)t * HIDK + c0) = o;
        }
    }

    {
        float acc[4][4];
#pragma unroll
        for (int i = 0; i < 4; i++)
#pragma unroll
            for (int j = 0; j < 4; j++) acc[i][j] = 0.f;
        for (int s = 0; s < CT; s++) {
            float4 a = *(float4*)&sU[s * PD + r0];
            float4 bb = *(float4*)&sK[s * PD + c0];
            float av[4] = {a.x, a.y, a.z, a.w};
            float bv[4] = {bb.x, bb.y, bb.z, bb.w};
#pragma unroll
            for (int i = 0; i < 4; i++)
#pragma unroll
                for (int j = 0; j < 4; j++) acc[i][j] = fmaf(av[i], bv[j], acc[i][j]);
        }
        size_t pbase = ((size_t)(bh * NCH + c)) << 12;
#pragma unroll
        for (int i = 0; i < 4; i++) {
            float ev = sED[63 * PD + r0 + i];
            float4 o = make_float4(acc[i][0] * ev, acc[i][1] * ev, acc[i][2] * ev,
                                   acc[i][3] * ev);
            *(float4*)(g_P + pbase + ((size_t)(r0 + i) << 6) + c0) = o;
        }
    }
}

// ---------------- kernel B: scan over chunk states (k-split) ---------------
__global__ void __launch_bounds__(512) chunkscan_kernel() {
    int ks = blockIdx.x;   // 0..3
    int bh = blockIdx.y;
    int b = bh >> 4, h = bh & 15;
    int tid = threadIdx.x;
    int v = tid >> 3;
    int k = ks * 16 + (tid & 7) * 2;
    float2 S = make_float2(0.f, 0.f);

    for (int c = 0; c < NCH; c++) {
        size_t base = (((size_t)(bh * NCH + c)) << 12) + ((size_t)v << 6) + k;
        *(float2*)(g_S + base) = S;
        float E = g_expD[((size_t)(b * LSEQ + c * CT + 63)) * HIDK + h * HDIM + v];
        float2 p = *(float2*)(g_P + base);
        S.x = fmaf(S.x, E, p.x);
        S.y = fmaf(S.y, E, p.y);
    }
}

// ---------------- kernel C: inter-chunk output ------------------------------
__global__ void __launch_bounds__(256) inter_kernel() {
    __shared__ float sQt[64 * PD];
    __shared__ float sSt[64 * PD];
    int c = blockIdx.x, bh = blockIdx.y;
    int b = bh >> 4, h = bh & 15;
    int tid = threadIdx.x;
    size_t rowbase = (size_t)(b * LSEQ + c * CT) * HIDK + h * HDIM;
    size_t sbase = ((size_t)(bh * NCH + c)) << 12;

#pragma unroll
    for (int i = 0; i < 4; i++) {
        int idx = tid + i * 256;
        int t = idx >> 4, c4 = (idx & 15) << 2;
        float4 q4 = *(const float4*)(g_q + rowbase + (size_t)t * HIDK + c4);
        sQt[(c4 + 0) * PD + t] = q4.x;
        sQt[(c4 + 1) * PD + t] = q4.y;
        sQt[(c4 + 2) * PD + t] = q4.z;
        sQt[(c4 + 3) * PD + t] = q4.w;
        float4 s4 = *(const float4*)(g_S + sbase + ((size_t)t << 6) + c4);
        sSt[(c4 + 0) * PD + t] = s4.x;
        sSt[(c4 + 1) * PD + t] = s4.y;
        sSt[(c4 + 2) * PD + t] = s4.z;
        sSt[(c4 + 3) * PD + t] = s4.w;
    }
    __syncthreads();

    int t0 = (tid >> 4) << 2, v0 = (tid & 15) << 2;
    float acc[4][4];
#pragma unroll
    for (int i = 0; i < 4; i++)
#pragma unroll
        for (int j = 0; j < 4; j++) acc[i][j] = 0.f;
    for (int k = 0; k < 64; k++) {
        float4 a = *(float4*)&sQt[k * PD + t0];
        float4 bb = *(float4*)&sSt[k * PD + v0];
        float av[4] = {a.x, a.y, a.z, a.w};
        float bv[4] = {bb.x, bb.y, bb.z, bb.w};
#pragma unroll
        for (int i = 0; i < 4; i++)
#pragma unroll
            for (int j = 0; j < 4; j++) acc[i][j] = fmaf(av[i], bv[j], acc[i][j]);
    }
#pragma unroll
    for (int i = 0; i < 4; i++) {
        int t = t0 + i;
        size_t gi = rowbase + (size_t)t * HIDK + v0;
        float4 e = *(float4*)(g_expD + gi);
        float4 o = *(float4*)(g_att + gi);
        o.x = fmaf(acc[i][0], e.x, o.x);
        o.y = fmaf(acc[i][1], e.y, o.y);
        o.z = fmaf(acc[i][2], e.z, o.z);
        o.w = fmaf(acc[i][3], e.w, o.w);
        *(float4*)(g_att + gi) = o;
    }
}

// ---------------- LayerNorm + SiLU gate -> fp16 y (+ scaled copy) ----------
__global__ void __launch_bounds__(256) ln_gate_kernel(const float* __restrict__ gamma,
                                                      const float* __restrict__ beta) {
    int row = blockIdx.x;
    int tid = threadIdx.x;
    const float* a = g_att + (size_t)row * HIDK;
    float vals[4];
    float s = 0.f, s2 = 0.f;
#pragma unroll
    for (int i = 0; i < 4; i++) {
        vals[i] = a[i * 256 + tid];
        s += vals[i];
        s2 = fmaf(vals[i], vals[i], s2);
    }
#pragma unroll
    for (int o = 16; o; o >>= 1) {
        s += __shfl_xor_sync(0xffffffffu, s, o);
        s2 += __shfl_xor_sync(0xffffffffu, s2, o);
    }
    __shared__ float rs[8], rs2[8];
    int warp = tid >> 5;
    if ((tid & 31) == 0) { rs[warp] = s; rs2[warp] = s2; }
    __syncthreads();
    s = 0.f;
    s2 = 0.f;
#pragma unroll
    for (int w = 0; w < 8; w++) { s += rs[w]; s2 += rs2[w]; }
    float mean = s * (1.f / HIDK);
    float var = s2 * (1.f / HIDK) - mean * mean;
    float rstd = rsqrtf(var + 1e-5f);
#pragma unroll
    for (int i = 0; i < 4; i++) {
        int col = i * 256 + tid;
        float gv = g_xg[(size_t)row * HIDK + col];
        float sil = gv / (1.f + __expf(-gv));
        float yv = ((vals[i] - mean) * rstd * gamma[col] + beta[col]) * sil;
        g_yh[(size_t)row * HIDK + col] = __float2half(yv);
        g_ys[(size_t)row * HIDK + col] = __float2half(yv * SC_DN);
    }
}

// ---------------- launch --------------------------------------------------
extern "C" void kernel_launch(void* const* d_in, const int* in_sizes, int n_in,
                              void* d_out, int out_size) {
    const float* x = (const float*)d_in[0];
    const float* Wq = (const float*)d_in[1];
    const float* Wk = (const float*)d_in[2];
    const float* Wv = (const float*)d_in[3];
    const float* Wg = (const float*)d_in[4];
    const float* Wgk1 = (const float*)d_in[5];
    const float* Wgk2 = (const float*)d_in[6];
    const float* bgk2 = (const float*)d_in[7];
    const float* gamma = (const float*)d_in[8];
    const float* beta = (const float*)d_in[9];
    const float* Wout = (const float*)d_in[10];
    float* out = (float*)d_out;

    const int SMEM_A = 6 * 64 * PD * sizeof(float);
    cudaFuncSetAttribute(chunk_kernel, cudaFuncAttributeMaxDynamicSharedMemorySize, SMEM_A);
    cudaFuncSetAttribute(mmproj_kernel, cudaFuncAttributeMaxDynamicSharedMemorySize, SMEM_MM);
    cudaFuncSetAttribute(mmout_kernel, cudaFuncAttributeMaxDynamicSharedMemorySize, SMEM_MM);
    cudaFuncSetAttribute(lr_fused_kernel, cudaFuncAttributeMaxDynamicSharedMemorySize, SMEM_LR);

    xconv_kernel<<<MTOK * HIDK / 1024, 256>>>(x);
    wconv_kernel<<<dim3(32, 32, 5), 256>>>(Wq, Wk, Wv, Wg, Wout);
    lr_fused_kernel<<<MTOK / 16, 256, SMEM_LR>>>(x, Wgk1, Wgk2, bgk2);

    mmproj_kernel<<<dim3(8, 32, 4), 256, SMEM_MM>>>();

    chunk_kernel<<<dim3(NCH, 32), 256, SMEM_A>>>();
    chunkscan_kernel<<<dim3(4, 32), 512>>>();
    inter_kernel<<<dim3(NCH, 32), 256>>>();
    ln_gate_kernel<<<MTOK, 256>>>(gamma, beta);

    mmout_kernel<<<dim3(8, 32, 1), 256, SMEM_MM>>>(out);
}

// round 8
// speedup vs baseline: 1.5883x; 1.1055x over previous
#include <cuda_runtime.h>
#include <cuda_fp16.h>
#include <math.h>
#include <stdint.h>

#define HIDK 1024
#define MTOK 4096
#define LSEQ 2048
#define NHEAD 16
#define HDIM 64
#define CT 64
#define NCH (LSEQ / CT)
#define PD 68
#define PDH 72

// ---------------- scratch (device globals; no allocations) ----------------
__device__ float g_q[MTOK * HIDK];
__device__ float g_k[MTOK * HIDK];
__device__ float g_v[MTOK * HIDK];
__device__ float g_xg[MTOK * HIDK];
__device__ float g_gk[MTOK * HIDK];
__device__ float g_att[MTOK * HIDK];
__device__ float g_expD[MTOK * HIDK];
__device__ float g_P[32 * NCH * HDIM * HDIM];
__device__ float g_S[32 * NCH * HDIM * HDIM];
// fp16 operands: activations single + 2^-10-scaled copy; weights exact pair
__device__ __align__(16) __half g_xh[MTOK * HIDK];
__device__ __align__(16) __half g_xs[MTOK * HIDK];   // x * 2^-10
__device__ __align__(16) __half g_yh[MTOK * HIDK];
__device__ __align__(16) __half g_ys[MTOK * HIDK];   // y * 2^-10
__device__ __align__(16) __half g_wh[5 * HIDK * HIDK];  // transposed [n][k], round(W)
__device__ __align__(16) __half g_wl[5 * HIDK * HIDK];  // (W - Wh) * 2^10

// ======================= helpers =======================
__device__ __forceinline__ uint32_t smem_u32(const void* p) {
    uint32_t a;
    asm("{ .reg .u64 t; cvta.to.shared.u64 t, %1; cvt.u32.u64 %0, t; }" : "=r"(a) : "l"(p));
    return a;
}
__device__ __forceinline__ void cpasync16(uint32_t s, const void* g) {
    asm volatile("cp.async.cg.shared.global [%0], [%1], 16;" ::"r"(s), "l"(g));
}
__device__ __forceinline__ void cpcommit() { asm volatile("cp.async.commit_group;"); }

__device__ __forceinline__ void ldmx4(uint32_t& r0, uint32_t& r1, uint32_t& r2,
                                      uint32_t& r3, uint32_t addr) {
    asm volatile("ldmatrix.sync.aligned.m8n8.x4.shared.b16 {%0,%1,%2,%3}, [%4];"
                 : "=r"(r0), "=r"(r1), "=r"(r2), "=r"(r3)
                 : "r"(addr));
}
__device__ __forceinline__ void ldmx4t(uint32_t& r0, uint32_t& r1, uint32_t& r2,
                                       uint32_t& r3, uint32_t addr) {
    asm volatile("ldmatrix.sync.aligned.m8n8.x4.trans.shared.b16 {%0,%1,%2,%3}, [%4];"
                 : "=r"(r0), "=r"(r1), "=r"(r2), "=r"(r3)
                 : "r"(addr));
}
__device__ __forceinline__ void mma16816(float* c, const uint32_t* a, const uint32_t* b) {
    asm volatile(
        "mma.sync.aligned.m16n8k16.row.col.f32.f16.f16.f32 "
        "{%0,%1,%2,%3}, {%4,%5,%6,%7}, {%8,%9}, {%0,%1,%2,%3};"
        : "+f"(c[0]), "+f"(c[1]), "+f"(c[2]), "+f"(c[3])
        : "r"(a[0]), "r"(a[1]), "r"(a[2]), "r"(a[3]), "r"(b[0]), "r"(b[1]));
}

// ======================= fp16 mma.sync big GEMM (unchanged R7) ==============
#define ROWB 80
#define STG_A (128 * ROWB)
#define STG (2 * STG_A)
#define NSTG 4
#define SMEM_MM (NSTG * STG)
#define NSTAGES 64

__device__ __forceinline__ void mm_issue(int s, uint32_t sb, int tid, int brow, int bcol,
                                         const __half* Ah, const __half* As,
                                         const __half* Bh, const __half* Bl) {
    if (s < NSTAGES) {
        int p = s >> 5;
        int kk = (s & 31) << 5;
        const __half* Ab = p ? As : Ah;
        const __half* Bb = p ? Bl : Bh;
        uint32_t st = sb + (uint32_t)(s & 3) * STG;
        int row = tid >> 2, cw = tid & 3;
        const char* ga = (const char*)(Ab + (size_t)(brow + row) * HIDK + kk + cw * 8);
        cpasync16(st + row * ROWB + cw * 16, ga);
        cpasync16(st + (row + 64) * ROWB + cw * 16, ga + (size_t)64 * HIDK * 2);
        const char* gb = (const char*)(Bb + (size_t)(bcol + row) * HIDK + kk + cw * 8);
        cpasync16(st + STG_A + row * ROWB + cw * 16, gb);
        cpasync16(st + STG_A + (row + 64) * ROWB + cw * 16, gb + (size_t)64 * HIDK * 2);
    }
    cpcommit();
}

__device__ __forceinline__ void mma_gemm_body(const __half* __restrict__ Ah,
                                              const __half* __restrict__ As,
                                              const __half* __restrict__ Bh,
                                              const __half* __restrict__ Bl,
                                              float* __restrict__ C) {
    extern __shared__ char sm_raw[];
    uint32_t sb = smem_u32(sm_raw);
    int tid = threadIdx.x, lane = tid & 31, wid = tid >> 5;
    int wm = wid & 3, wn = wid >> 2;
    int brow = blockIdx.y * 128, bcol = blockIdx.x * 128;

    float c[2][8][4];
#pragma unroll
    for (int i = 0; i < 2; i++)
#pragma unroll
        for (int j = 0; j < 8; j++)
#pragma unroll
            for (int l = 0; l < 4; l++) c[i][j][l] = 0.f;

    mm_issue(0, sb, tid, brow, bcol, Ah, As, Bh, Bl);
    mm_issue(1, sb, tid, brow, bcol, Ah, As, Bh, Bl);
    mm_issue(2, sb, tid, brow, bcol, Ah, As, Bh, Bl);

    int q = lane >> 3, r = lane & 7;

    for (int s = 0; s < NSTAGES; s++) {
        asm volatile("cp.async.wait_group 2;" ::: "memory");
        __syncthreads();
        uint32_t st = sb + (uint32_t)(s & 3) * STG;
        uint32_t sA = st, sB = st + STG_A;
#pragma unroll
        for (int k0 = 0; k0 < 32; k0 += 16) {
            uint32_t a[2][4], b[8][2];
#pragma unroll
            for (int mf = 0; mf < 2; mf++) {
                int rrow = wm * 32 + mf * 16 + (q & 1) * 8 + r;
                int kc = k0 + (q >> 1) * 8;
                ldmx4(a[mf][0], a[mf][1], a[mf][2], a[mf][3], sA + rrow * ROWB + kc * 2);
            }
#pragma unroll
            for (int pb = 0; pb < 4; pb++) {
                int nrow = wn * 64 + pb * 16 + (q >> 1) * 8 + r;
                int kc = k0 + (q & 1) * 8;
                uint32_t r0, r1, r2, r3;
                ldmx4(r0, r1, r2, r3, sB + nrow * ROWB + kc * 2);
                b[pb * 2][0] = r0;
                b[pb * 2][1] = r1;
                b[pb * 2 + 1][0] = r2;
                b[pb * 2 + 1][1] = r3;
            }
#pragma unroll
            for (int mf = 0; mf < 2; mf++)
#pragma unroll
                for (int nf = 0; nf < 8; nf++) mma16816(c[mf][nf], a[mf], b[nf]);
        }
        mm_issue(s + 3, sb, tid, brow, bcol, Ah, As, Bh, Bl);
    }

    int qr = lane >> 2, qc = lane & 3;
#pragma unroll
    for (int mf = 0; mf < 2; mf++)
#pragma unroll
        for (int nf = 0; nf < 8; nf++) {
            int row0 = brow + wm * 32 + mf * 16 + qr;
            int col = bcol + wn * 64 + nf * 8 + qc * 2;
            *(float2*)&C[(size_t)row0 * HIDK + col] = make_float2(c[mf][nf][0], c[mf][nf][1]);
            *(float2*)&C[(size_t)(row0 + 8) * HIDK + col] = make_float2(c[mf][nf][2], c[mf][nf][3]);
        }
}

__global__ void __launch_bounds__(256, 2) mmproj_kernel() {
    int z = blockIdx.z;
    const __half* Bh = g_wh + (size_t)z * HIDK * HIDK;
    const __half* Bl = g_wl + (size_t)z * HIDK * HIDK;
    float* C = (z == 0) ? g_q : (z == 1) ? g_k : (z == 2) ? g_v : g_xg;
    mma_gemm_body(g_xh, g_xs, Bh, Bl, C);
}
__global__ void __launch_bounds__(256, 2) mmout_kernel(float* __restrict__ out) {
    mma_gemm_body(g_yh, g_ys, g_wh + (size_t)4 * HIDK * HIDK,
                  g_wl + (size_t)4 * HIDK * HIDK, out);
}

// ======================= conversion kernels (unchanged) =====================
#define SC_DN (1.f / 1024.f)
__global__ void __launch_bounds__(256) xconv_kernel(const float* __restrict__ x) {
    size_t i = (size_t)blockIdx.x * 256 + threadIdx.x;
    float4 v = ((const float4*)x)[i];
    __half2* ph = (__half2*)g_xh;
    __half2* ps = (__half2*)g_xs;
    ph[2 * i] = __halves2half2(__float2half(v.x), __float2half(v.y));
    ph[2 * i + 1] = __halves2half2(__float2half(v.z), __float2half(v.w));
    ps[2 * i] = __halves2half2(__float2half(v.x * SC_DN), __float2half(v.y * SC_DN));
    ps[2 * i + 1] = __halves2half2(__float2half(v.z * SC_DN), __float2half(v.w * SC_DN));
}

__global__ void __launch_bounds__(256) wconv_kernel(const float* __restrict__ W0,
                                                    const float* __restrict__ W1,
                                                    const float* __restrict__ W2,
                                                    const float* __restrict__ W3,
                                                    const float* __restrict__ W4) {
    int z = blockIdx.z;
    const float* W = (z == 0) ? W0 : (z == 1) ? W1 : (z == 2) ? W2 : (z == 3) ? W3 : W4;
    __half* Th = g_wh + (size_t)z * HIDK * HIDK;
    __half* Tl = g_wl + (size_t)z * HIDK * HIDK;
    __shared__ float t[32][33];
    int n0 = blockIdx.x * 32, k0 = blockIdx.y * 32;
    int lx = threadIdx.x & 31, ly = threadIdx.x >> 5;
#pragma unroll
    for (int i = 0; i < 4; i++) {
        int r = ly + i * 8;
        t[r][lx] = W[(size_t)(k0 + r) * HIDK + n0 + lx];
    }
    __syncthreads();
#pragma unroll
    for (int i = 0; i < 4; i++) {
        int r = ly + i * 8;
        float v = t[lx][r];
        __half h = __float2half(v);
        size_t o = (size_t)(n0 + r) * HIDK + k0 + lx;
        Th[o] = h;
        Tl[o] = __float2half((v - __half2float(h)) * 1024.f);
    }
}

// ---------------- fused low-rank gate path (unchanged) ---------------------
#define SMEM_LR (32 * 1024 * sizeof(float))
__global__ void __launch_bounds__(256) lr_fused_kernel(const float* __restrict__ x,
                                                       const float* __restrict__ W1,
                                                       const float* __restrict__ W2,
                                                       const float* __restrict__ bias) {
    extern __shared__ float s[];
    float* w1s = s;
    float* w2s = s + 16384;
    __shared__ float ts[16][17];
    int tid = threadIdx.x;
#pragma unroll
    for (int i = 0; i < 16; i++) {
        int idx = tid + i * 256;
        ((float4*)w1s)[idx] = ((const float4*)W1)[idx];
        ((float4*)w2s)[idx] = ((const float4*)W2)[idx];
    }
    __syncthreads();

    int m0 = blockIdx.x * 16;
    {
        int mt = tid >> 4, r = tid & 15;
        const float* xr = x + (size_t)(m0 + mt) * HIDK;
        float acc = 0.f;
#pragma unroll 8
        for (int kk = 0; kk < HIDK; kk++) acc = fmaf(xr[kk], w1s[kk * 16 + r], acc);
        ts[mt][r] = acc;
    }
    __syncthreads();

    int n = tid * 4;
    float4 b4 = *(const float4*)(bias + n);
#pragma unroll 1
    for (int mi = 0; mi < 16; mi++) {
        float4 a = b4;
#pragma unroll
        for (int rr = 0; rr < 16; rr++) {
            float tv = ts[mi][rr];
            float4 w = *(float4*)&w2s[rr * 1024 + n];
            a.x = fmaf(tv, w.x, a.x);
            a.y = fmaf(tv, w.y, a.y);
            a.z = fmaf(tv, w.z, a.z);
            a.w = fmaf(tv, w.w, a.w);
        }
        float4 o;
        o.x = (fminf(a.x, 0.f) - __logf(1.f + __expf(-fabsf(a.x)))) * 0.0625f;
        o.y = (fminf(a.y, 0.f) - __logf(1.f + __expf(-fabsf(a.y)))) * 0.0625f;
        o.z = (fminf(a.z, 0.f) - __logf(1.f + __expf(-fabsf(a.z)))) * 0.0625f;
        o.w = (fminf(a.w, 0.f) - __logf(1.f + __expf(-fabsf(a.w)))) * 0.0625f;
        *(float4*)(g_gk + (size_t)(m0 + mi) * HIDK + n) = o;
    }
}

// ---------------- chunked GLA: kernel A — fp16 tensor cores -----------------
// smem: sGf fp32 [64][68] (becomes expD), sVf fp32 [64][68],
//       Qh/Kh/Uh/Ah fp16 [64][72]
#define OFF_V 17408
#define OFF_Q 34816
#define OFF_K 44032
#define OFF_U 53248
#define OFF_A 62464
#define SMEM_CH 71680

__global__ void __launch_bounds__(256) chunk_kernel() {
    extern __shared__ char smc[];
    float* sGf = (float*)smc;
    float* sVf = (float*)(smc + OFF_V);
    uint32_t sb = smem_u32(smc);
    uint32_t Qb = sb + OFF_Q, Kb = sb + OFF_K, Ub = sb + OFF_U, Ab = sb + OFF_A;
    __half* QhP = (__half*)(smc + OFF_Q);
    __half* KhP = (__half*)(smc + OFF_K);
    __half* UhP = (__half*)(smc + OFF_U);
    __half* AhP = (__half*)(smc + OFF_A);
    __shared__ float sTot[4][64];

    int c = blockIdx.x, bh = blockIdx.y;
    int b = bh >> 4, h = bh & 15;
    int tid = threadIdx.x;
    size_t rowbase = (size_t)(b * LSEQ + c * CT) * HIDK + h * HDIM;

    // stage: q,k -> fp16; g,v -> fp32
#pragma unroll
    for (int i = 0; i < 4; i++) {
        int idx = tid + i * 256;
        int t = idx >> 4, c4 = (idx & 15) << 2;
        size_t gi = rowbase + (size_t)t * HIDK + c4;
        float4 q4 = *(const float4*)(g_q + gi);
        float4 k4 = *(const float4*)(g_k + gi);
        float4 v4 = *(const float4*)(g_v + gi);
        float4 g4 = *(const float4*)(g_gk + gi);
        *(__half2*)&QhP[t * PDH + c4] = __halves2half2(__float2half(q4.x), __float2half(q4.y));
        *(__half2*)&QhP[t * PDH + c4 + 2] = __halves2half2(__float2half(q4.z), __float2half(q4.w));
        *(__half2*)&KhP[t * PDH + c4] = __halves2half2(__float2half(k4.x), __float2half(k4.y));
        *(__half2*)&KhP[t * PDH + c4 + 2] = __halves2half2(__float2half(k4.z), __float2half(k4.w));
        *(float4*)&sGf[t * PD + c4] = g4;
        *(float4*)&sVf[t * PD + c4] = v4;
    }
    __syncthreads();

    // segment-parallel cumsum -> sGf = exp(D), Uh = fp16(exp(-D)*v)
    {
        int ch = tid & 63, seg = tid >> 6;
        int t0s = seg * 16;
        float run = 0.f;
#pragma unroll
        for (int t = t0s; t < t0s + 16; t++) {
            run += sGf[t * PD + ch];
            sGf[t * PD + ch] = run;
        }
        sTot[seg][ch] = run;
    }
    __syncthreads();
    {
        int ch = tid & 63, seg = tid >> 6;
        float off = 0.f;
        if (seg > 0) off += sTot[0][ch];
        if (seg > 1) off += sTot[1][ch];
        if (seg > 2) off += sTot[2][ch];
        int t0s = seg * 16;
#pragma unroll
        for (int t = t0s; t < t0s + 16; t++) {
            float D = sGf[t * PD + ch] + off;
            sGf[t * PD + ch] = __expf(D);
            UhP[t * PDH + ch] = __float2half(__expf(-D) * sVf[t * PD + ch]);
        }
    }
    __syncthreads();

    // write exp(D) to global
#pragma unroll
    for (int i = 0; i < 4; i++) {
        int idx = tid + i * 256;
        int t = idx >> 4, c4 = (idx & 15) << 2;
        *(float4*)(g_expD + rowbase + (size_t)t * HIDK + c4) = *(float4*)&sGf[t * PD + c4];
    }

    int w = tid >> 5, l = tid & 31;
    int m0 = (w & 3) << 4, n0h = (w >> 2) << 5;
    int lr2 = l >> 2, lc2 = (l & 3) << 1;

    // ---- GEMM1: A[t,s] = Q.K^T, masked -> Ah [t][s] fp16 ----
    {
        float cc[4][4];
#pragma unroll
        for (int i = 0; i < 4; i++)
#pragma unroll
            for (int j = 0; j < 4; j++) cc[i][j] = 0.f;
#pragma unroll
        for (int k0 = 0; k0 < 64; k0 += 16) {
            uint32_t a[4], b0[4], b1[4];
            ldmx4(a[0], a[1], a[2], a[3],
                  Qb + ((m0 + (l & 15)) * PDH + k0 + ((l & 16) ? 8 : 0)) * 2);
            ldmx4(b0[0], b0[1], b0[2], b0[3],
                  Kb + ((n0h + (l & 7) + ((l & 16) ? 8 : 0)) * PDH + k0 + ((l & 8) ? 8 : 0)) * 2);
            ldmx4(b1[0], b1[1], b1[2], b1[3],
                  Kb + ((n0h + 16 + (l & 7) + ((l & 16) ? 8 : 0)) * PDH + k0 + ((l & 8) ? 8 : 0)) * 2);
            mma16816(cc[0], a, &b0[0]);
            mma16816(cc[1], a, &b0[2]);
            mma16816(cc[2], a, &b1[0]);
            mma16816(cc[3], a, &b1[2]);
        }
        int tr = m0 + lr2;
#pragma unroll
        for (int nf = 0; nf < 4; nf++) {
            int sc = n0h + nf * 8 + lc2;
            *(__half2*)&AhP[tr * PDH + sc] = __halves2half2(
                __float2half(sc <= tr ? cc[nf][0] : 0.f),
                __float2half(sc + 1 <= tr ? cc[nf][1] : 0.f));
            int tr2 = tr + 8;
            *(__half2*)&AhP[tr2 * PDH + sc] = __halves2half2(
                __float2half(sc <= tr2 ? cc[nf][2] : 0.f),
                __float2half(sc + 1 <= tr2 ? cc[nf][3] : 0.f));
        }
    }
    __syncthreads();

    // ---- GEMM2: o_intra[t,v] = sum_s A'[t,s] U[s,v]; scale expD, store ----
    {
        float cc[4][4];
#pragma unroll
        for (int i = 0; i < 4; i++)
#pragma unroll
            for (int j = 0; j < 4; j++) cc[i][j] = 0.f;
#pragma unroll
        for (int s0 = 0; s0 < 64; s0 += 16) {
            uint32_t a[4], b0[4], b1[4];
            ldmx4(a[0], a[1], a[2], a[3],
                  Ab + ((m0 + (l & 15)) * PDH + s0 + ((l & 16) ? 8 : 0)) * 2);
            ldmx4t(b0[0], b0[1], b0[2], b0[3],
                   Ub + ((s0 + (l & 15)) * PDH + n0h + ((l & 16) ? 8 : 0)) * 2);
            ldmx4t(b1[0], b1[1], b1[2], b1[3],
                   Ub + ((s0 + (l & 15)) * PDH + n0h + 16 + ((l & 16) ? 8 : 0)) * 2);
            mma16816(cc[0], a, &b0[0]);
            mma16816(cc[1], a, &b0[2]);
            mma16816(cc[2], a, &b1[0]);
            mma16816(cc[3], a, &b1[2]);
        }
        int tr = m0 + lr2;
#pragma unroll
        for (int nf = 0; nf < 4; nf++) {
            int v = n0h + nf * 8 + lc2;
            float2 e0 = *(float2*)&sGf[tr * PD + v];
            *(float2*)(g_att + rowbase + (size_t)tr * HIDK + v) =
                make_float2(cc[nf][0] * e0.x, cc[nf][1] * e0.y);
            float2 e1 = *(float2*)&sGf[(tr + 8) * PD + v];
            *(float2*)(g_att + rowbase + (size_t)(tr + 8) * HIDK + v) =
                make_float2(cc[nf][2] * e1.x, cc[nf][3] * e1.y);
        }
    }

    // ---- GEMM3: P[v,kd] = sum_s U[s,v] K[s,kd]; scale expD_end, store ----
    {
        float cc[4][4];
#pragma unroll
        for (int i = 0; i < 4; i++)
#pragma unroll
            for (int j = 0; j < 4; j++) cc[i][j] = 0.f;
#pragma unroll
        for (int s0 = 0; s0 < 64; s0 += 16) {
            uint32_t a[4], b0[4], b1[4];
            ldmx4t(a[0], a[1], a[2], a[3],
                   Ub + ((s0 + (l & 7) + ((l & 16) ? 8 : 0)) * PDH + m0 + ((l & 8) ? 8 : 0)) * 2);
            ldmx4t(b0[0], b0[1], b0[2], b0[3],
                   Kb + ((s0 + (l & 15)) * PDH + n0h + ((l & 16) ? 8 : 0)) * 2);
            ldmx4t(b1[0], b1[1], b1[2], b1[3],
                   Kb + ((s0 + (l & 15)) * PDH + n0h + 16 + ((l & 16) ? 8 : 0)) * 2);
            mma16816(cc[0], a, &b0[0]);
            mma16816(cc[1], a, &b0[2]);
            mma16816(cc[2], a, &b1[0]);
            mma16816(cc[3], a, &b1[2]);
        }
        size_t pbase = ((size_t)(bh * NCH + c)) << 12;
        int vr = m0 + lr2;
        float ev0 = sGf[63 * PD + vr];
        float ev1 = sGf[63 * PD + vr + 8];
#pragma unroll
        for (int nf = 0; nf < 4; nf++) {
            int kd = n0h + nf * 8 + lc2;
            *(float2*)(g_P + pbase + ((size_t)vr << 6) + kd) =
                make_float2(cc[nf][0] * ev0, cc[nf][1] * ev0);
            *(float2*)(g_P + pbase + ((size_t)(vr + 8) << 6) + kd) =
                make_float2(cc[nf][2] * ev1, cc[nf][3] * ev1);
        }
    }
}

// ---------------- kernel B: scan over chunk states (k-split) ---------------
__global__ void __launch_bounds__(512) chunkscan_kernel() {
    int ks = blockIdx.x;
    int bh = blockIdx.y;
    int b = bh >> 4, h = bh & 15;
    int tid = threadIdx.x;
    int v = tid >> 3;
    int k = ks * 16 + (tid & 7) * 2;
    float2 S = make_float2(0.f, 0.f);

    for (int c = 0; c < NCH; c++) {
        size_t base = (((size_t)(bh * NCH + c)) << 12) + ((size_t)v << 6) + k;
        *(float2*)(g_S + base) = S;
        float E = g_expD[((size_t)(b * LSEQ + c * CT + 63)) * HIDK + h * HDIM + v];
        float2 p = *(float2*)(g_P + base);
        S.x = fmaf(S.x, E, p.x);
        S.y = fmaf(S.y, E, p.y);
    }
}

// ---------------- kernel C: inter-chunk output — fp16 tensor cores ---------
__global__ void __launch_bounds__(256) inter_kernel() {
    __shared__ __align__(16) __half sQ[64 * PDH];
    __shared__ __align__(16) __half sS[64 * PDH];
    int c = blockIdx.x, bh = blockIdx.y;
    int b = bh >> 4, h = bh & 15;
    int tid = threadIdx.x;
    size_t rowbase = (size_t)(b * LSEQ + c * CT) * HIDK + h * HDIM;
    size_t sbase = ((size_t)(bh * NCH + c)) << 12;
    uint32_t Qb = smem_u32(sQ), Sb = smem_u32(sS);

#pragma unroll
    for (int i = 0; i < 4; i++) {
        int idx = tid + i * 256;
        int t = idx >> 4, c4 = (idx & 15) << 2;
        float4 q4 = *(const float4*)(g_q + rowbase + (size_t)t * HIDK + c4);
        *(__half2*)&sQ[t * PDH + c4] = __halves2half2(__float2half(q4.x), __float2half(q4.y));
        *(__half2*)&sQ[t * PDH + c4 + 2] = __halves2half2(__float2half(q4.z), __float2half(q4.w));
        float4 s4 = *(const float4*)(g_S + sbase + ((size_t)t << 6) + c4);
        *(__half2*)&sS[t * PDH + c4] = __halves2half2(__float2half(s4.x), __float2half(s4.y));
        *(__half2*)&sS[t * PDH + c4 + 2] = __halves2half2(__float2half(s4.z), __float2half(s4.w));
    }
    __syncthreads();

    int w = tid >> 5, l = tid & 31;
    int m0 = (w & 3) << 4, n0h = (w >> 2) << 5;
    int lr2 = l >> 2, lc2 = (l & 3) << 1;

    float cc[4][4];
#pragma unroll
    for (int i = 0; i < 4; i++)
#pragma unroll
        for (int j = 0; j < 4; j++) cc[i][j] = 0.f;
#pragma unroll
    for (int k0 = 0; k0 < 64; k0 += 16) {
        uint32_t a[4], b0[4], b1[4];
        ldmx4(a[0], a[1], a[2], a[3],
              Qb + ((m0 + (l & 15)) * PDH + k0 + ((l & 16) ? 8 : 0)) * 2);
        ldmx4(b0[0], b0[1], b0[2], b0[3],
              Sb + ((n0h + (l & 7) + ((l & 16) ? 8 : 0)) * PDH + k0 + ((l & 8) ? 8 : 0)) * 2);
        ldmx4(b1[0], b1[1], b1[2], b1[3],
              Sb + ((n0h + 16 + (l & 7) + ((l & 16) ? 8 : 0)) * PDH + k0 + ((l & 8) ? 8 : 0)) * 2);
        mma16816(cc[0], a, &b0[0]);
        mma16816(cc[1], a, &b0[2]);
        mma16816(cc[2], a, &b1[0]);
        mma16816(cc[3], a, &b1[2]);
    }
    int tr = m0 + lr2;
#pragma unroll
    for (int nf = 0; nf < 4; nf++) {
        int v = n0h + nf * 8 + lc2;
        size_t gi0 = rowbase + (size_t)tr * HIDK + v;
        float2 e0 = *(float2*)(g_expD + gi0);
        float2 o0 = *(float2*)(g_att + gi0);
        o0.x = fmaf(cc[nf][0], e0.x, o0.x);
        o0.y = fmaf(cc[nf][1], e0.y, o0.y);
        *(float2*)(g_att + gi0) = o0;
        size_t gi1 = rowbase + (size_t)(tr + 8) * HIDK + v;
        float2 e1 = *(float2*)(g_expD + gi1);
        float2 o1 = *(float2*)(g_att + gi1);
        o1.x = fmaf(cc[nf][2], e1.x, o1.x);
        o1.y = fmaf(cc[nf][3], e1.y, o1.y);
        *(float2*)(g_att + gi1) = o1;
    }
}

// ---------------- LayerNorm + SiLU gate -> fp16 y (+ scaled copy) ----------
__global__ void __launch_bounds__(256) ln_gate_kernel(const float* __restrict__ gamma,
                                                      const float* __restrict__ beta) {
    int row = blockIdx.x;
    int tid = threadIdx.x;
    const float* a = g_att + (size_t)row * HIDK;
    float vals[4];
    float s = 0.f, s2 = 0.f;
#pragma unroll
    for (int i = 0; i < 4; i++) {
        vals[i] = a[i * 256 + tid];
        s += vals[i];
        s2 = fmaf(vals[i], vals[i], s2);
    }
#pragma unroll
    for (int o = 16; o; o >>= 1) {
        s += __shfl_xor_sync(0xffffffffu, s, o);
        s2 += __shfl_xor_sync(0xffffffffu, s2, o);
    }
    __shared__ float rs[8], rs2[8];
    int warp = tid >> 5;
    if ((tid & 31) == 0) { rs[warp] = s; rs2[warp] = s2; }
    __syncthreads();
    s = 0.f;
    s2 = 0.f;
#pragma unroll
    for (int w = 0; w < 8; w++) { s += rs[w]; s2 += rs2[w]; }
    float mean = s * (1.f / HIDK);
    float var = s2 * (1.f / HIDK) - mean * mean;
    float rstd = rsqrtf(var + 1e-5f);
#pragma unroll
    for (int i = 0; i < 4; i++) {
        int col = i * 256 + tid;
        float gv = g_xg[(size_t)row * HIDK + col];
        float sil = gv / (1.f + __expf(-gv));
        float yv = ((vals[i] - mean) * rstd * gamma[col] + beta[col]) * sil;
        g_yh[(size_t)row * HIDK + col] = __float2half(yv);
        g_ys[(size_t)row * HIDK + col] = __float2half(yv * SC_DN);
    }
}

// ---------------- launch --------------------------------------------------
extern "C" void kernel_launch(void* const* d_in, const int* in_sizes, int n_in,
                              void* d_out, int out_size) {
    const float* x = (const float*)d_in[0];
    const float* Wq = (const float*)d_in[1];
    const float* Wk = (const float*)d_in[2];
    const float* Wv = (const float*)d_in[3];
    const float* Wg = (const float*)d_in[4];
    const float* Wgk1 = (const float*)d_in[5];
    const float* Wgk2 = (const float*)d_in[6];
    const float* bgk2 = (const float*)d_in[7];
    const float* gamma = (const float*)d_in[8];
    const float* beta = (const float*)d_in[9];
    const float* Wout = (const float*)d_in[10];
    float* out = (float*)d_out;

    cudaFuncSetAttribute(chunk_kernel, cudaFuncAttributeMaxDynamicSharedMemorySize, SMEM_CH);
    cudaFuncSetAttribute(mmproj_kernel, cudaFuncAttributeMaxDynamicSharedMemorySize, SMEM_MM);
    cudaFuncSetAttribute(mmout_kernel, cudaFuncAttributeMaxDynamicSharedMemorySize, SMEM_MM);
    cudaFuncSetAttribute(lr_fused_kernel, cudaFuncAttributeMaxDynamicSharedMemorySize, SMEM_LR);

    xconv_kernel<<<MTOK * HIDK / 1024, 256>>>(x);
    wconv_kernel<<<dim3(32, 32, 5), 256>>>(Wq, Wk, Wv, Wg, Wout);
    lr_fused_kernel<<<MTOK / 16, 256, SMEM_LR>>>(x, Wgk1, Wgk2, bgk2);

    mmproj_kernel<<<dim3(8, 32, 4), 256, SMEM_MM>>>();

    chunk_kernel<<<dim3(NCH, 32), 256, SMEM_CH>>>();
    chunkscan_kernel<<<dim3(4, 32), 512>>>();
    inter_kernel<<<dim3(NCH, 32), 256>>>();
    ln_gate_kernel<<<MTOK, 256>>>(gamma, beta);

    mmout_kernel<<<dim3(8, 32, 1), 256, SMEM_MM>>>(out);
}